// round 10
// baseline (speedup 1.0000x reference)
#include <cuda_runtime.h>
#include <math.h>
#include <stdint.h>

// ---------------- problem dims ----------------
#define TT 128
#define NN 1024
#define HH 512
#define II 64
#define G3 1536
#define NSTRIP 16
#define NKSTG 16
#define NTH 256

// ---------------- device scratch ----------------
// weights: [strip][kstage][96 rows][32 k]; rows cr = hgrp*24 + gate*8 + e,
// k XOR-swizzled by 8*(cr&3)
__device__ float g_Whh2[NSTRIP * NKSTG * 96 * 32];
__device__ float g_Wih_t[G3 * II];
__device__ float g_hA2[2][NKSTG * NN * 32];
__device__ float g_Gi[(size_t)TT * NSTRIP * NN * 96];   // [t][strip][n][96 cr-order]

// ---------------- helpers ----------------
__device__ __forceinline__ uint32_t f2tf32(float f) {
    uint32_t r;
    asm("cvt.rna.tf32.f32 %0, %1;" : "=r"(r) : "f"(f));
    return r;
}
__device__ __forceinline__ uint32_t smem_u32(const void* p) {
    uint32_t a;
    asm("{ .reg .u64 t; cvta.to.shared.u64 t, %1; cvt.u32.u64 %0, t; }" : "=r"(a) : "l"(p));
    return a;
}
__device__ __forceinline__ float sigf(float x) { return 1.0f / (1.0f + __expf(-x)); }

#define MBARRIER_INIT(addr, cnt) \
    asm volatile("mbarrier.init.shared.b64 [%0], %1;" :: "r"(addr), "r"(cnt) : "memory")
#define MBARRIER_ARRIVE(addr) \
    asm volatile("mbarrier.arrive.shared.b64 _, [%0];" :: "r"(addr) : "memory")
#define MBARRIER_EXPECT_TX(addr, tx) \
    asm volatile("mbarrier.arrive.expect_tx.shared.b64 _, [%0], %1;" \
                 :: "r"(addr), "r"(tx) : "memory")
#define MBARRIER_WAIT_PARITY(mbar_addr, phase_parity) do {                                 \
    uint32_t _mbar = (uint32_t)(mbar_addr);                                                \
    uint32_t _parity = (uint32_t)(phase_parity);                                           \
    uint32_t _done;                                                                        \
    asm volatile(                                                                          \
        "{\n\t.reg .pred p;\n\t"                                                           \
        "mbarrier.try_wait.parity.acquire.cta.shared::cta.b64 p, [%1], %2;\n\t"            \
        "selp.b32 %0, 1, 0, p;\n\t}"                                                       \
        : "=r"(_done) : "r"(_mbar), "r"(_parity) : "memory");                              \
    if (!_done) {                                                                          \
        asm volatile(                                                                      \
            "{\n\t.reg .pred P1;\n\t"                                                      \
            "WAIT_LOOP_%=:\n\t"                                                            \
            "mbarrier.try_wait.parity.acquire.cta.shared::cta.b64 P1, [%0], %1, 0x989680;\n\t" \
            "@P1 bra.uni WAIT_DONE_%=;\n\t"                                                \
            "bra.uni WAIT_LOOP_%=;\n\t"                                                    \
            "WAIT_DONE_%=:\n\t}"                                                           \
            :: "r"(_mbar), "r"(_parity) : "memory");                                       \
    }                                                                                      \
} while (0)

#define BULK_G2S(dst_smem, src_gmem, bytes, mbar) \
    asm volatile("cp.async.bulk.shared::cluster.global.mbarrier::complete_tx::bytes " \
                 "[%0], [%1], %2, [%3];" \
                 :: "r"(dst_smem), "l"(src_gmem), "r"(bytes), "r"(mbar) : "memory")

__device__ __forceinline__ void mma_tf32(float (&c)[4], uint32_t a0, uint32_t a1,
                                         uint32_t a2, uint32_t a3,
                                         uint32_t b0, uint32_t b1) {
    asm volatile(
        "mma.sync.aligned.m16n8k8.row.col.f32.tf32.tf32.f32 "
        "{%0,%1,%2,%3}, {%4,%5,%6,%7}, {%8,%9}, {%0,%1,%2,%3};"
        : "+f"(c[0]), "+f"(c[1]), "+f"(c[2]), "+f"(c[3])
        : "r"(a0), "r"(a1), "r"(a2), "r"(a3), "r"(b0), "r"(b1));
}

// ================= prep: cr = hgrp*24 + gate*8 + e ordering =================
__global__ void prep_kernel(const float* __restrict__ W_hh,
                            const float* __restrict__ W_ih,
                            const float* __restrict__ hxs) {
    int idx = blockIdx.x * blockDim.x + threadIdx.x;
    if (idx < G3 * HH) {
        int r = idx >> 9, k = idx & 511;
        int gg = r >> 9, u = r & 511, s = u >> 5, c = u & 31;
        int cr = (c >> 3) * 24 + gg * 8 + (c & 7);
        int kst = k >> 5, kk = k & 31;
        g_Whh2[((s * NKSTG + kst) * 96 + cr) * 32 + (kk ^ (8 * (cr & 3)))] =
            __uint_as_float(f2tf32(W_hh[idx]));
    }
    if (idx < G3 * II) g_Wih_t[idx] = __uint_as_float(f2tf32(W_ih[idx]));
    if (idx < NN * HH) {
        int n = idx >> 9, k = idx & 511;
        int kst = k >> 5, kk = k & 31;
        g_hA2[0][(kst * NN + n) * 32 + (kk ^ (8 * (n & 3)))] =
            __uint_as_float(f2tf32(hxs[idx]));
    }
}

// ================= Gi precompute (cr ordering matching prep) =================
#define GI_SST 68
__global__ __launch_bounds__(256, 1)
void gi_kernel(const float* __restrict__ X) {
    extern __shared__ float sm[];
    float* Xs = sm;
    float* Ws = sm + 128 * GI_SST;
    const int tid = threadIdx.x;
    const int rb = blockIdx.y * 128;
    const int cb = blockIdx.x * 128;

    #pragma unroll
    for (int it = 0; it < 8; it++) {
        int id = it * 256 + tid;
        int row = id >> 4, c4 = (id & 15) * 4;
        float4 v = *reinterpret_cast<const float4*>(X + (size_t)(rb + row) * II + c4);
        uint4 o = make_uint4(f2tf32(v.x), f2tf32(v.y), f2tf32(v.z), f2tf32(v.w));
        *reinterpret_cast<uint4*>(Xs + row * GI_SST + c4) = o;
        float4 w = *reinterpret_cast<const float4*>(g_Wih_t + (size_t)(cb + row) * II + c4);
        *reinterpret_cast<float4*>(Ws + row * GI_SST + c4) = w;
    }
    __syncthreads();

    const int w = tid >> 5, lane = tid & 31, g = lane >> 2, t = lane & 3;
    const int wr = w & 3, wc = w >> 2;
    float acc[2][8][4];
    #pragma unroll
    for (int sl = 0; sl < 2; sl++)
        #pragma unroll
        for (int j = 0; j < 8; j++)
            #pragma unroll
            for (int q = 0; q < 4; q++) acc[sl][j][q] = 0.0f;

    #pragma unroll
    for (int k8 = 0; k8 < 8; k8++) {
        const int kb = k8 * 8;
        uint32_t a[2][4], b[8][2];
        #pragma unroll
        for (int sl = 0; sl < 2; sl++) {
            int m0 = wr * 32 + sl * 16;
            a[sl][0] = __float_as_uint(Xs[(m0 + g) * GI_SST + kb + t]);
            a[sl][1] = __float_as_uint(Xs[(m0 + 8 + g) * GI_SST + kb + t]);
            a[sl][2] = __float_as_uint(Xs[(m0 + g) * GI_SST + kb + t + 4]);
            a[sl][3] = __float_as_uint(Xs[(m0 + 8 + g) * GI_SST + kb + t + 4]);
        }
        #pragma unroll
        for (int j = 0; j < 8; j++) {
            int n0 = wc * 64 + j * 8;
            b[j][0] = __float_as_uint(Ws[(n0 + g) * GI_SST + kb + t]);
            b[j][1] = __float_as_uint(Ws[(n0 + g) * GI_SST + kb + t + 4]);
        }
        #pragma unroll
        for (int sl = 0; sl < 2; sl++)
            #pragma unroll
            for (int j = 0; j < 8; j++)
                mma_tf32(acc[sl][j], a[sl][0], a[sl][1], a[sl][2], a[sl][3],
                         b[j][0], b[j][1]);
    }

    #pragma unroll
    for (int sl = 0; sl < 2; sl++) {
        #pragma unroll
        for (int j = 0; j < 8; j++) {
            int row = rb + wr * 32 + sl * 16 + g;
            int col = cb + wc * 64 + j * 8 + 2 * t;
            int tt = row >> 10, n = row & 1023;
            int gg = col >> 9, hcol = col & 511, s = hcol >> 5, cl = hcol & 31;
            int cr = (cl >> 3) * 24 + gg * 8 + (cl & 7);
            size_t base0 = (((size_t)tt * NSTRIP + s) * NN + n) * 96 + cr;
            *reinterpret_cast<float2*>(g_Gi + base0) =
                make_float2(acc[sl][j][0], acc[sl][j][1]);
            size_t base1 = (((size_t)tt * NSTRIP + s) * NN + (n + 8)) * 96 + cr;
            *reinterpret_cast<float2*>(g_Gi + base1) =
                make_float2(acc[sl][j][2], acc[sl][j][3]);
        }
    }
}

// ================= per-step kernel: M=64, R2C4, fragment epilogue =================
#define NBUF 4
#define A_STG_B 8192                   // 64 rows x 32 k x 4
#define B_STG_B 12288                  // 96 rows x 32 k x 4
#define STG_B (A_STG_B + B_STG_B)      // 20480
#define EPI_GI (NBUF * STG_B)          // 81920 : [64][96] f32 = 24576
#define MB_OFF (EPI_GI + 24576)        // mbF[4] @0, mbE[4] @32, mbGi @64
#define SMEM_STEP (MB_OFF + 96)        // 106592 -> 2 CTAs/SM

__global__ __launch_bounds__(NTH, 2)
void gru_step(const float* __restrict__ hA,      // [kst][1024][32]
              float* __restrict__ hA_next,
              const float* __restrict__ h_prev,  // fp32 [1024][512]
              const float* __restrict__ m_t,
              const float* __restrict__ Gi_t,    // [strip][1024][96] (this t)
              const float* __restrict__ Whh2,
              const float* __restrict__ b_ih,
              const float* __restrict__ b_hh,
              float* __restrict__ h_out,
              float* __restrict__ h_out2) {
    extern __shared__ char smem[];
    const uint32_t sbase = smem_u32(smem);
    const int tid = threadIdx.x;
    const int strip = blockIdx.x;      // 0..15
    const int rb = blockIdx.y * 64;    // 0..960

    const uint32_t mbF = sbase + MB_OFF;
    const uint32_t mbE = mbF + 32;
    const uint32_t mbGi = mbF + 64;

    const int w = tid >> 5, lane = tid & 31, g = lane >> 2, t = lane & 3;
    const int wr = w & 1, wc = w >> 1;        // 2 rowgroups x 4 colgroups
    const int r00 = wr * 32 + g;              // frag0 base row
    const int r10 = r00 + 16;                 // frag1 base row
    const int crb = wc * 24 + g;              // B row base (gate stride 8)
    const int sw0 = 8 * (g & 3);
    const int hc = wc * 8 + 2 * t;            // output col pair within strip

    if (tid == 0) {
        #pragma unroll
        for (int i = 0; i < NBUF; i++) {
            MBARRIER_INIT(mbF + 8 * i, 1);
            MBARRIER_INIT(mbE + 8 * i, 8);    // one arrive per warp
        }
        MBARRIER_INIT(mbGi, 1);
    }
    __syncthreads();

    const float* Bsrc = Whh2 + (size_t)strip * NKSTG * 96 * 32;
    if (tid == 0) {
        #pragma unroll
        for (int s = 0; s < NBUF; s++) {
            MBARRIER_EXPECT_TX(mbF + 8 * s, STG_B);
            BULK_G2S(sbase + s * STG_B, hA + ((size_t)s * NN + rb) * 32, A_STG_B,
                     mbF + 8 * s);
            BULK_G2S(sbase + s * STG_B + A_STG_B, Bsrc + (size_t)s * 96 * 32, B_STG_B,
                     mbF + 8 * s);
        }
        MBARRIER_EXPECT_TX(mbGi, 24576);
        BULK_G2S(sbase + EPI_GI, Gi_t + ((size_t)strip * NN + rb) * 96, 24576, mbGi);
    }

    // ---- epilogue operand preloads (registers; overlap with mainloop) ----
    float mreg[2][2];
    float2 hpr[2][2];
    #pragma unroll
    for (int f = 0; f < 2; f++)
        #pragma unroll
        for (int rs = 0; rs < 2; rs++) {
            const int R = rb + wr * 32 + f * 16 + g + 8 * rs;
            mreg[f][rs] = m_t[R];
            hpr[f][rs] = *reinterpret_cast<const float2*>(
                &h_prev[(size_t)R * HH + strip * 32 + hc]);
        }

    float acc[2][3][4];
    #pragma unroll
    for (int f = 0; f < 2; f++)
        #pragma unroll
        for (int j = 0; j < 3; j++)
            #pragma unroll
            for (int q = 0; q < 4; q++) acc[f][j][q] = 0.0f;

    // ---- mainloop: no __syncthreads; warp-skewed full/empty ring ----
    for (int s = 0; s < NKSTG; s++) {
        const int buf = s & 3;
        const int ph = (s >> 2) & 1;
        MBARRIER_WAIT_PARITY(mbF + 8 * buf, ph);
        const float* As = (const float*)(smem + buf * STG_B);
        const float* Bs = (const float*)(smem + buf * STG_B + A_STG_B);
        #pragma unroll
        for (int kb = 0; kb < 2; kb++) {
            const int koff = (kb * 16 + 4 * t) ^ sw0;
            float4 a00 = *reinterpret_cast<const float4*>(&As[r00 * 32 + koff]);
            float4 a01 = *reinterpret_cast<const float4*>(&As[(r00 + 8) * 32 + koff]);
            float4 a10 = *reinterpret_cast<const float4*>(&As[r10 * 32 + koff]);
            float4 a11 = *reinterpret_cast<const float4*>(&As[(r10 + 8) * 32 + koff]);
            float4 b0 = *reinterpret_cast<const float4*>(&Bs[crb * 32 + koff]);
            float4 b1 = *reinterpret_cast<const float4*>(&Bs[(crb + 8) * 32 + koff]);
            float4 b2 = *reinterpret_cast<const float4*>(&Bs[(crb + 16) * 32 + koff]);
            // sub-MMA 0: k = {4t, 4t+1}
            mma_tf32(acc[0][0], __float_as_uint(a00.x), __float_as_uint(a01.x),
                     __float_as_uint(a00.y), __float_as_uint(a01.y),
                     __float_as_uint(b0.x), __float_as_uint(b0.y));
            mma_tf32(acc[0][1], __float_as_uint(a00.x), __float_as_uint(a01.x),
                     __float_as_uint(a00.y), __float_as_uint(a01.y),
                     __float_as_uint(b1.x), __float_as_uint(b1.y));
            mma_tf32(acc[0][2], __float_as_uint(a00.x), __float_as_uint(a01.x),
                     __float_as_uint(a00.y), __float_as_uint(a01.y),
                     __float_as_uint(b2.x), __float_as_uint(b2.y));
            mma_tf32(acc[1][0], __float_as_uint(a10.x), __float_as_uint(a11.x),
                     __float_as_uint(a10.y), __float_as_uint(a11.y),
                     __float_as_uint(b0.x), __float_as_uint(b0.y));
            mma_tf32(acc[1][1], __float_as_uint(a10.x), __float_as_uint(a11.x),
                     __float_as_uint(a10.y), __float_as_uint(a11.y),
                     __float_as_uint(b1.x), __float_as_uint(b1.y));
            mma_tf32(acc[1][2], __float_as_uint(a10.x), __float_as_uint(a11.x),
                     __float_as_uint(a10.y), __float_as_uint(a11.y),
                     __float_as_uint(b2.x), __float_as_uint(b2.y));
            // sub-MMA 1: k = {4t+2, 4t+3}
            mma_tf32(acc[0][0], __float_as_uint(a00.z), __float_as_uint(a01.z),
                     __float_as_uint(a00.w), __float_as_uint(a01.w),
                     __float_as_uint(b0.z), __float_as_uint(b0.w));
            mma_tf32(acc[0][1], __float_as_uint(a00.z), __float_as_uint(a01.z),
                     __float_as_uint(a00.w), __float_as_uint(a01.w),
                     __float_as_uint(b1.z), __float_as_uint(b1.w));
            mma_tf32(acc[0][2], __float_as_uint(a00.z), __float_as_uint(a01.z),
                     __float_as_uint(a00.w), __float_as_uint(a01.w),
                     __float_as_uint(b2.z), __float_as_uint(b2.w));
            mma_tf32(acc[1][0], __float_as_uint(a10.z), __float_as_uint(a11.z),
                     __float_as_uint(a10.w), __float_as_uint(a11.w),
                     __float_as_uint(b0.z), __float_as_uint(b0.w));
            mma_tf32(acc[1][1], __float_as_uint(a10.z), __float_as_uint(a11.z),
                     __float_as_uint(a10.w), __float_as_uint(a11.w),
                     __float_as_uint(b1.z), __float_as_uint(b1.w));
            mma_tf32(acc[1][2], __float_as_uint(a10.z), __float_as_uint(a11.z),
                     __float_as_uint(a10.w), __float_as_uint(a11.w),
                     __float_as_uint(b2.z), __float_as_uint(b2.w));
        }
        if (lane == 0) MBARRIER_ARRIVE(mbE + 8 * buf);
        if (tid == 0 && s + NBUF < NKSTG) {
            MBARRIER_WAIT_PARITY(mbE + 8 * buf, ph);   // all 8 warps done with buf
            MBARRIER_EXPECT_TX(mbF + 8 * buf, STG_B);
            BULK_G2S(sbase + buf * STG_B, hA + ((size_t)(s + NBUF) * NN + rb) * 32,
                     A_STG_B, mbF + 8 * buf);
            BULK_G2S(sbase + buf * STG_B + A_STG_B, Bsrc + (size_t)(s + NBUF) * 96 * 32,
                     B_STG_B, mbF + 8 * buf);
        }
    }

    // ---- fragment-direct epilogue ----
    MBARRIER_WAIT_PARITY(mbGi, 0);
    const float* sGi = (const float*)(smem + EPI_GI);
    const int gcol = strip * 32 + hc;
    const float2 bir = *reinterpret_cast<const float2*>(&b_ih[gcol]);
    const float2 biz = *reinterpret_cast<const float2*>(&b_ih[512 + gcol]);
    const float2 bin = *reinterpret_cast<const float2*>(&b_ih[1024 + gcol]);
    const float2 bhr = *reinterpret_cast<const float2*>(&b_hh[gcol]);
    const float2 bhz = *reinterpret_cast<const float2*>(&b_hh[512 + gcol]);
    const float2 bhn = *reinterpret_cast<const float2*>(&b_hh[1024 + gcol]);

    #pragma unroll
    for (int f = 0; f < 2; f++) {
        #pragma unroll
        for (int rs = 0; rs < 2; rs++) {
            const int Rl = wr * 32 + f * 16 + g + 8 * rs;   // local row
            const int R = rb + Rl;
            const float m = mreg[f][rs];
            const float2 gr = *reinterpret_cast<const float2*>(
                &sGi[Rl * 96 + wc * 24 + 2 * t]);
            const float2 gz = *reinterpret_cast<const float2*>(
                &sGi[Rl * 96 + wc * 24 + 8 + 2 * t]);
            const float2 gn = *reinterpret_cast<const float2*>(
                &sGi[Rl * 96 + wc * 24 + 16 + 2 * t]);
            const float sr0 = acc[f][0][2 * rs], sr1 = acc[f][0][2 * rs + 1];
            const float sz0 = acc[f][1][2 * rs], sz1 = acc[f][1][2 * rs + 1];
            const float sn0 = acc[f][2][2 * rs], sn1 = acc[f][2][2 * rs + 1];
            const float2 hp = hpr[f][rs];

            float rv0 = sigf(fmaf(m, sr0 + gr.x, bir.x + bhr.x));
            float rv1 = sigf(fmaf(m, sr1 + gr.y, bir.y + bhr.y));
            float zv0 = sigf(fmaf(m, sz0 + gz.x, biz.x + bhz.x));
            float zv1 = sigf(fmaf(m, sz1 + gz.y, biz.y + bhz.y));
            float nv0 = tanhf(fmaf(m, gn.x, bin.x) + rv0 * fmaf(m, sn0, bhn.x));
            float nv1 = tanhf(fmaf(m, gn.y, bin.y) + rv1 * fmaf(m, sn1, bhn.y));
            float h0 = fmaf(zv0, fmaf(m, hp.x, -nv0), nv0);
            float h1 = fmaf(zv1, fmaf(m, hp.y, -nv1), nv1);

            *reinterpret_cast<float2*>(&h_out[(size_t)R * HH + gcol]) =
                make_float2(h0, h1);
            if (h_out2)
                *reinterpret_cast<float2*>(&h_out2[(size_t)R * HH + gcol]) =
                    make_float2(h0, h1);
            uint2 oc = make_uint2(f2tf32(h0), f2tf32(h1));
            *reinterpret_cast<uint2*>(
                &hA_next[((size_t)strip * NN + R) * 32 + (hc ^ sw0)]) = oc;
        }
    }
}

// ---------------- host ----------------
extern "C" void kernel_launch(void* const* d_in, const int* in_sizes, int n_in,
                              void* d_out, int out_size) {
    const float* hxs   = (const float*)d_in[0];
    const float* masks = (const float*)d_in[2];
    const float* pact  = (const float*)d_in[3];
    const float* W_ih  = (const float*)d_in[4];
    const float* W_hh  = (const float*)d_in[5];
    const float* b_ih  = (const float*)d_in[6];
    const float* b_hh  = (const float*)d_in[7];
    float* out = (float*)d_out;

    static bool attr_set = false;
    if (!attr_set) {
        cudaFuncSetAttribute(gi_kernel, cudaFuncAttributeMaxDynamicSharedMemorySize,
                             2 * 128 * GI_SST * 4);
        cudaFuncSetAttribute(gru_step, cudaFuncAttributeMaxDynamicSharedMemorySize,
                             SMEM_STEP);
        attr_set = true;
    }

    static float* hA0 = nullptr;
    static float* gGi = nullptr;
    static float* gW2 = nullptr;
    if (!hA0) cudaGetSymbolAddress((void**)&hA0, g_hA2);
    if (!gGi) cudaGetSymbolAddress((void**)&gGi, g_Gi);
    if (!gW2) cudaGetSymbolAddress((void**)&gW2, g_Whh2);

    // 1) prep
    prep_kernel<<<(G3 * HH + 255) / 256, 256>>>(W_hh, W_ih, hxs);

    // 2) Gi
    {
        dim3 grid(G3 / 128, (TT * NN) / 128);
        gi_kernel<<<grid, 256, 2 * 128 * GI_SST * 4>>>(pact);
    }

    // 3) sequential steps
    const size_t stepElems = (size_t)NN * HH;
    const size_t hASz = (size_t)NKSTG * NN * 32;
    const bool has_tail = (size_t)out_size >= (size_t)TT * stepElems + stepElems;

    dim3 grid(NSTRIP, NN / 64);                  // (16, 16) = 256 CTAs, 2/SM
    for (int tstep = 0; tstep < TT; tstep++) {
        const float* h_prev = (tstep == 0) ? hxs : out + (size_t)(tstep - 1) * stepElems;
        float* h_out  = out + (size_t)tstep * stepElems;
        float* h_out2 = (tstep == TT - 1 && has_tail) ? out + (size_t)TT * stepElems
                                                      : nullptr;
        const float* hA_cur  = hA0 + (size_t)(tstep & 1) * hASz;
        float*       hA_next = hA0 + (size_t)((tstep + 1) & 1) * hASz;
        gru_step<<<grid, NTH, SMEM_STEP>>>(
            hA_cur, hA_next, h_prev,
            masks + (size_t)tstep * NN,
            gGi + (size_t)tstep * NSTRIP * NN * 96,
            gW2, b_ih, b_hh, h_out, h_out2);
    }
}

// round 11
// speedup vs baseline: 1.3003x; 1.3003x over previous
#include <cuda_runtime.h>
#include <math.h>
#include <stdint.h>

// ---------------- problem dims ----------------
#define TT 128
#define NN 1024
#define HH 512
#define II 64
#define G3 1536
#define NSTRIP 16
#define NKSTG 16
#define NTH 256

// ---------------- device scratch ----------------
// weights: [strip][kstage][96 rows][32 k]; rows cr = hgrp*24 + gate*8 + e,
// k XOR-swizzled by 8*(cr&3)
__device__ float g_Whh2[NSTRIP * NKSTG * 96 * 32];
__device__ float g_Wih_t[G3 * II];
__device__ float g_hA2[2][NKSTG * NN * 32];
__device__ float g_Gi[(size_t)TT * NSTRIP * NN * 96];   // [t][strip][n][96 cr-order]

// ---------------- helpers ----------------
__device__ __forceinline__ uint32_t f2tf32(float f) {
    uint32_t r;
    asm("cvt.rna.tf32.f32 %0, %1;" : "=r"(r) : "f"(f));
    return r;
}
__device__ __forceinline__ uint32_t smem_u32(const void* p) {
    uint32_t a;
    asm("{ .reg .u64 t; cvta.to.shared.u64 t, %1; cvt.u32.u64 %0, t; }" : "=r"(a) : "l"(p));
    return a;
}
__device__ __forceinline__ float sigf(float x) { return 1.0f / (1.0f + __expf(-x)); }

#define MBARRIER_INIT(addr, cnt) \
    asm volatile("mbarrier.init.shared.b64 [%0], %1;" :: "r"(addr), "r"(cnt) : "memory")
#define MBARRIER_EXPECT_TX(addr, tx) \
    asm volatile("mbarrier.arrive.expect_tx.shared.b64 _, [%0], %1;" \
                 :: "r"(addr), "r"(tx) : "memory")
#define MBARRIER_WAIT_PARITY(mbar_addr, phase_parity) do {                                 \
    uint32_t _mbar = (uint32_t)(mbar_addr);                                                \
    uint32_t _parity = (uint32_t)(phase_parity);                                           \
    uint32_t _done;                                                                        \
    asm volatile(                                                                          \
        "{\n\t.reg .pred p;\n\t"                                                           \
        "mbarrier.try_wait.parity.acquire.cta.shared::cta.b64 p, [%1], %2;\n\t"            \
        "selp.b32 %0, 1, 0, p;\n\t}"                                                       \
        : "=r"(_done) : "r"(_mbar), "r"(_parity) : "memory");                              \
    if (!_done) {                                                                          \
        asm volatile(                                                                      \
            "{\n\t.reg .pred P1;\n\t"                                                      \
            "WAIT_LOOP_%=:\n\t"                                                            \
            "mbarrier.try_wait.parity.acquire.cta.shared::cta.b64 P1, [%0], %1, 0x989680;\n\t" \
            "@P1 bra.uni WAIT_DONE_%=;\n\t"                                                \
            "bra.uni WAIT_LOOP_%=;\n\t"                                                    \
            "WAIT_DONE_%=:\n\t}"                                                           \
            :: "r"(_mbar), "r"(_parity) : "memory");                                       \
    }                                                                                      \
} while (0)

#define BULK_G2S(dst_smem, src_gmem, bytes, mbar) \
    asm volatile("cp.async.bulk.shared::cluster.global.mbarrier::complete_tx::bytes " \
                 "[%0], [%1], %2, [%3];" \
                 :: "r"(dst_smem), "l"(src_gmem), "r"(bytes), "r"(mbar) : "memory")

__device__ __forceinline__ void mma_tf32(float (&c)[4], uint32_t a0, uint32_t a1,
                                         uint32_t a2, uint32_t a3,
                                         uint32_t b0, uint32_t b1) {
    asm volatile(
        "mma.sync.aligned.m16n8k8.row.col.f32.tf32.tf32.f32 "
        "{%0,%1,%2,%3}, {%4,%5,%6,%7}, {%8,%9}, {%0,%1,%2,%3};"
        : "+f"(c[0]), "+f"(c[1]), "+f"(c[2]), "+f"(c[3])
        : "r"(a0), "r"(a1), "r"(a2), "r"(a3), "r"(b0), "r"(b1));
}

// ================= prep: cr = hgrp*24 + gate*8 + e ordering =================
__global__ void prep_kernel(const float* __restrict__ W_hh,
                            const float* __restrict__ W_ih,
                            const float* __restrict__ hxs) {
    int idx = blockIdx.x * blockDim.x + threadIdx.x;
    if (idx < G3 * HH) {
        int r = idx >> 9, k = idx & 511;
        int gg = r >> 9, u = r & 511, s = u >> 5, c = u & 31;
        int cr = (c >> 3) * 24 + gg * 8 + (c & 7);
        int kst = k >> 5, kk = k & 31;
        g_Whh2[((s * NKSTG + kst) * 96 + cr) * 32 + (kk ^ (8 * (cr & 3)))] =
            __uint_as_float(f2tf32(W_hh[idx]));
    }
    if (idx < G3 * II) g_Wih_t[idx] = __uint_as_float(f2tf32(W_ih[idx]));
    if (idx < NN * HH) {
        int n = idx >> 9, k = idx & 511;
        int kst = k >> 5, kk = k & 31;
        g_hA2[0][(kst * NN + n) * 32 + (kk ^ (8 * (n & 3)))] =
            __uint_as_float(f2tf32(hxs[idx]));
    }
}

// ================= Gi precompute (cr ordering matching prep) =================
#define GI_SST 68
__global__ __launch_bounds__(256, 1)
void gi_kernel(const float* __restrict__ X) {
    extern __shared__ float sm[];
    float* Xs = sm;
    float* Ws = sm + 128 * GI_SST;
    const int tid = threadIdx.x;
    const int rb = blockIdx.y * 128;
    const int cb = blockIdx.x * 128;

    #pragma unroll
    for (int it = 0; it < 8; it++) {
        int id = it * 256 + tid;
        int row = id >> 4, c4 = (id & 15) * 4;
        float4 v = *reinterpret_cast<const float4*>(X + (size_t)(rb + row) * II + c4);
        uint4 o = make_uint4(f2tf32(v.x), f2tf32(v.y), f2tf32(v.z), f2tf32(v.w));
        *reinterpret_cast<uint4*>(Xs + row * GI_SST + c4) = o;
        float4 w = *reinterpret_cast<const float4*>(g_Wih_t + (size_t)(cb + row) * II + c4);
        *reinterpret_cast<float4*>(Ws + row * GI_SST + c4) = w;
    }
    __syncthreads();

    const int w = tid >> 5, lane = tid & 31, g = lane >> 2, t = lane & 3;
    const int wr = w & 3, wc = w >> 2;
    float acc[2][8][4];
    #pragma unroll
    for (int sl = 0; sl < 2; sl++)
        #pragma unroll
        for (int j = 0; j < 8; j++)
            #pragma unroll
            for (int q = 0; q < 4; q++) acc[sl][j][q] = 0.0f;

    #pragma unroll
    for (int k8 = 0; k8 < 8; k8++) {
        const int kb = k8 * 8;
        uint32_t a[2][4], b[8][2];
        #pragma unroll
        for (int sl = 0; sl < 2; sl++) {
            int m0 = wr * 32 + sl * 16;
            a[sl][0] = __float_as_uint(Xs[(m0 + g) * GI_SST + kb + t]);
            a[sl][1] = __float_as_uint(Xs[(m0 + 8 + g) * GI_SST + kb + t]);
            a[sl][2] = __float_as_uint(Xs[(m0 + g) * GI_SST + kb + t + 4]);
            a[sl][3] = __float_as_uint(Xs[(m0 + 8 + g) * GI_SST + kb + t + 4]);
        }
        #pragma unroll
        for (int j = 0; j < 8; j++) {
            int n0 = wc * 64 + j * 8;
            b[j][0] = __float_as_uint(Ws[(n0 + g) * GI_SST + kb + t]);
            b[j][1] = __float_as_uint(Ws[(n0 + g) * GI_SST + kb + t + 4]);
        }
        #pragma unroll
        for (int sl = 0; sl < 2; sl++)
            #pragma unroll
            for (int j = 0; j < 8; j++)
                mma_tf32(acc[sl][j], a[sl][0], a[sl][1], a[sl][2], a[sl][3],
                         b[j][0], b[j][1]);
    }

    #pragma unroll
    for (int sl = 0; sl < 2; sl++) {
        #pragma unroll
        for (int j = 0; j < 8; j++) {
            int row = rb + wr * 32 + sl * 16 + g;
            int col = cb + wc * 64 + j * 8 + 2 * t;
            int tt = row >> 10, n = row & 1023;
            int gg = col >> 9, hcol = col & 511, s = hcol >> 5, cl = hcol & 31;
            int cr = (cl >> 3) * 24 + gg * 8 + (cl & 7);
            size_t base0 = (((size_t)tt * NSTRIP + s) * NN + n) * 96 + cr;
            *reinterpret_cast<float2*>(g_Gi + base0) =
                make_float2(acc[sl][j][0], acc[sl][j][1]);
            size_t base1 = (((size_t)tt * NSTRIP + s) * NN + (n + 8)) * 96 + cr;
            *reinterpret_cast<float2*>(g_Gi + base1) =
                make_float2(acc[sl][j][2], acc[sl][j][3]);
        }
    }
}

// ================= per-step kernel: M=64, 2x4 split, fragment epilogue =================
#define NBUF 3
#define A_STG_B 8192                   // 64 rows x 32 k x 4
#define B_STG_B 12288                  // 96 rows x 32 k x 4
#define STG_B (A_STG_B + B_STG_B)      // 20480
#define EPI_GI (NBUF * STG_B)          // 61440 : [64][96] f32 = 24576
#define MB_OFF (EPI_GI + 24576)        // mbF[3] @0, mbGi @24
#define SMEM_STEP (MB_OFF + 64)        // ~86 KB -> 2 CTAs/SM

__global__ __launch_bounds__(NTH, 2)
void gru_step(const float* __restrict__ hA,      // [kst][1024][32]
              float* __restrict__ hA_next,
              const float* __restrict__ h_prev,  // fp32 [1024][512]
              const float* __restrict__ m_t,
              const float* __restrict__ Gi_t,    // [strip][1024][96] (this t)
              const float* __restrict__ Whh2,
              const float* __restrict__ b_ih,
              const float* __restrict__ b_hh,
              float* __restrict__ h_out,
              float* __restrict__ h_out2) {
    extern __shared__ char smem[];
    const uint32_t sbase = smem_u32(smem);
    const int tid = threadIdx.x;
    const int strip = blockIdx.x;      // 0..15
    const int rb = blockIdx.y * 64;    // 0..960

    const uint32_t mbF = sbase + MB_OFF;
    const uint32_t mbGi = mbF + 24;

    const int w = tid >> 5, lane = tid & 31, g = lane >> 2, t = lane & 3;
    const int wr = w & 1, wc = w >> 1;        // 2 rowgroups(32) x 4 colgroups(24)
    const int r00 = wr * 32 + g;              // frag0 rows
    const int r10 = r00 + 16;                 // frag1 rows
    const int crb = wc * 24 + g;              // B rows: + gate*8
    const int sw0 = 8 * (g & 3);
    const int t2 = 2 * t;
    const int hc = wc * 8 + t2;               // output col pair within strip

    if (tid == 0) {
        #pragma unroll
        for (int i = 0; i < NBUF; i++) MBARRIER_INIT(mbF + 8 * i, 1);
        MBARRIER_INIT(mbGi, 1);
    }
    __syncthreads();

    const float* Bsrc = Whh2 + (size_t)strip * NKSTG * 96 * 32;
    if (tid == 0) {
        #pragma unroll
        for (int s = 0; s < NBUF; s++) {
            MBARRIER_EXPECT_TX(mbF + 8 * s, STG_B);
            BULK_G2S(sbase + s * STG_B, hA + ((size_t)s * NN + rb) * 32, A_STG_B,
                     mbF + 8 * s);
            BULK_G2S(sbase + s * STG_B + A_STG_B, Bsrc + (size_t)s * 96 * 32, B_STG_B,
                     mbF + 8 * s);
        }
        MBARRIER_EXPECT_TX(mbGi, 24576);
        BULK_G2S(sbase + EPI_GI, Gi_t + ((size_t)strip * NN + rb) * 96, 24576, mbGi);
    }

    // ---- epilogue operand preloads (registers; overlap with mainloop) ----
    float mreg[2][2];
    float2 hpr[2][2];
    #pragma unroll
    for (int f = 0; f < 2; f++)
        #pragma unroll
        for (int rs = 0; rs < 2; rs++) {
            const int R = rb + wr * 32 + f * 16 + g + 8 * rs;
            mreg[f][rs] = m_t[R];
            hpr[f][rs] = *reinterpret_cast<const float2*>(
                &h_prev[(size_t)R * HH + strip * 32 + hc]);
        }
    const int gcol = strip * 32 + hc;
    const float2 bir = *reinterpret_cast<const float2*>(&b_ih[gcol]);
    const float2 biz = *reinterpret_cast<const float2*>(&b_ih[512 + gcol]);
    const float2 bin = *reinterpret_cast<const float2*>(&b_ih[1024 + gcol]);
    const float2 bhr = *reinterpret_cast<const float2*>(&b_hh[gcol]);
    const float2 bhz = *reinterpret_cast<const float2*>(&b_hh[512 + gcol]);
    const float2 bhn = *reinterpret_cast<const float2*>(&b_hh[1024 + gcol]);

    float acc[2][3][4];     // [rowfrag][gate][quad]
    #pragma unroll
    for (int f = 0; f < 2; f++)
        #pragma unroll
        for (int j = 0; j < 3; j++)
            #pragma unroll
            for (int q = 0; q < 4; q++) acc[f][j][q] = 0.0f;

    // ---- mainloop: R9-style syncthreads ring, LDS.64 conflict-free loads ----
    for (int stg = 0; stg < NKSTG; stg++) {
        const int buf = stg % NBUF;
        MBARRIER_WAIT_PARITY(mbF + 8 * buf, (stg / NBUF) & 1);
        const float* As = (const float*)(smem + buf * STG_B);
        const float* Bs = (const float*)(smem + buf * STG_B + A_STG_B);
        #pragma unroll
        for (int k8 = 0; k8 < 4; k8++) {
            const int koff = (k8 * 8 + t2) ^ sw0;   // paired k' = 2t, 2t+1
            float2 a00 = *reinterpret_cast<const float2*>(&As[r00 * 32 + koff]);
            float2 a01 = *reinterpret_cast<const float2*>(&As[(r00 + 8) * 32 + koff]);
            float2 a10 = *reinterpret_cast<const float2*>(&As[r10 * 32 + koff]);
            float2 a11 = *reinterpret_cast<const float2*>(&As[(r10 + 8) * 32 + koff]);
            float2 b0 = *reinterpret_cast<const float2*>(&Bs[crb * 32 + koff]);
            float2 b1 = *reinterpret_cast<const float2*>(&Bs[(crb + 8) * 32 + koff]);
            float2 b2 = *reinterpret_cast<const float2*>(&Bs[(crb + 16) * 32 + koff]);
            mma_tf32(acc[0][0], __float_as_uint(a00.x), __float_as_uint(a01.x),
                     __float_as_uint(a00.y), __float_as_uint(a01.y),
                     __float_as_uint(b0.x), __float_as_uint(b0.y));
            mma_tf32(acc[0][1], __float_as_uint(a00.x), __float_as_uint(a01.x),
                     __float_as_uint(a00.y), __float_as_uint(a01.y),
                     __float_as_uint(b1.x), __float_as_uint(b1.y));
            mma_tf32(acc[0][2], __float_as_uint(a00.x), __float_as_uint(a01.x),
                     __float_as_uint(a00.y), __float_as_uint(a01.y),
                     __float_as_uint(b2.x), __float_as_uint(b2.y));
            mma_tf32(acc[1][0], __float_as_uint(a10.x), __float_as_uint(a11.x),
                     __float_as_uint(a10.y), __float_as_uint(a11.y),
                     __float_as_uint(b0.x), __float_as_uint(b0.y));
            mma_tf32(acc[1][1], __float_as_uint(a10.x), __float_as_uint(a11.x),
                     __float_as_uint(a10.y), __float_as_uint(a11.y),
                     __float_as_uint(b1.x), __float_as_uint(b1.y));
            mma_tf32(acc[1][2], __float_as_uint(a10.x), __float_as_uint(a11.x),
                     __float_as_uint(a10.y), __float_as_uint(a11.y),
                     __float_as_uint(b2.x), __float_as_uint(b2.y));
        }
        __syncthreads();
        if (tid == 0 && stg + NBUF < NKSTG) {
            const int s2 = stg + NBUF;
            MBARRIER_EXPECT_TX(mbF + 8 * buf, STG_B);
            BULK_G2S(sbase + buf * STG_B, hA + ((size_t)s2 * NN + rb) * 32, A_STG_B,
                     mbF + 8 * buf);
            BULK_G2S(sbase + buf * STG_B + A_STG_B, Bsrc + (size_t)s2 * 96 * 32,
                     B_STG_B, mbF + 8 * buf);
        }
    }

    // ---- fragment-direct epilogue ----
    MBARRIER_WAIT_PARITY(mbGi, 0);
    const float* sGi = (const float*)(smem + EPI_GI);

    #pragma unroll
    for (int f = 0; f < 2; f++) {
        #pragma unroll
        for (int rs = 0; rs < 2; rs++) {
            const int Rl = wr * 32 + f * 16 + g + 8 * rs;   // local row
            const int R = rb + Rl;
            const float m = mreg[f][rs];
            const float2 gr = *reinterpret_cast<const float2*>(
                &sGi[Rl * 96 + wc * 24 + t2]);
            const float2 gz = *reinterpret_cast<const float2*>(
                &sGi[Rl * 96 + wc * 24 + 8 + t2]);
            const float2 gn = *reinterpret_cast<const float2*>(
                &sGi[Rl * 96 + wc * 24 + 16 + t2]);
            const float sr0 = acc[f][0][2 * rs], sr1 = acc[f][0][2 * rs + 1];
            const float sz0 = acc[f][1][2 * rs], sz1 = acc[f][1][2 * rs + 1];
            const float sn0 = acc[f][2][2 * rs], sn1 = acc[f][2][2 * rs + 1];
            const float2 hp = hpr[f][rs];

            float rv0 = sigf(fmaf(m, sr0 + gr.x, bir.x + bhr.x));
            float rv1 = sigf(fmaf(m, sr1 + gr.y, bir.y + bhr.y));
            float zv0 = sigf(fmaf(m, sz0 + gz.x, biz.x + bhz.x));
            float zv1 = sigf(fmaf(m, sz1 + gz.y, biz.y + bhz.y));
            float nv0 = tanhf(fmaf(m, gn.x, bin.x) + rv0 * fmaf(m, sn0, bhn.x));
            float nv1 = tanhf(fmaf(m, gn.y, bin.y) + rv1 * fmaf(m, sn1, bhn.y));
            float h0 = fmaf(zv0, fmaf(m, hp.x, -nv0), nv0);
            float h1 = fmaf(zv1, fmaf(m, hp.y, -nv1), nv1);

            *reinterpret_cast<float2*>(&h_out[(size_t)R * HH + gcol]) =
                make_float2(h0, h1);
            if (h_out2)
                *reinterpret_cast<float2*>(&h_out2[(size_t)R * HH + gcol]) =
                    make_float2(h0, h1);
            uint2 oc = make_uint2(f2tf32(h0), f2tf32(h1));
            *reinterpret_cast<uint2*>(
                &hA_next[((size_t)strip * NN + R) * 32 + (hc ^ (8 * (R & 3)))]) = oc;
        }
    }
}

// ---------------- host ----------------
extern "C" void kernel_launch(void* const* d_in, const int* in_sizes, int n_in,
                              void* d_out, int out_size) {
    const float* hxs   = (const float*)d_in[0];
    const float* masks = (const float*)d_in[2];
    const float* pact  = (const float*)d_in[3];
    const float* W_ih  = (const float*)d_in[4];
    const float* W_hh  = (const float*)d_in[5];
    const float* b_ih  = (const float*)d_in[6];
    const float* b_hh  = (const float*)d_in[7];
    float* out = (float*)d_out;

    static bool attr_set = false;
    if (!attr_set) {
        cudaFuncSetAttribute(gi_kernel, cudaFuncAttributeMaxDynamicSharedMemorySize,
                             2 * 128 * GI_SST * 4);
        cudaFuncSetAttribute(gru_step, cudaFuncAttributeMaxDynamicSharedMemorySize,
                             SMEM_STEP);
        attr_set = true;
    }

    static float* hA0 = nullptr;
    static float* gGi = nullptr;
    static float* gW2 = nullptr;
    if (!hA0) cudaGetSymbolAddress((void**)&hA0, g_hA2);
    if (!gGi) cudaGetSymbolAddress((void**)&gGi, g_Gi);
    if (!gW2) cudaGetSymbolAddress((void**)&gW2, g_Whh2);

    // 1) prep
    prep_kernel<<<(G3 * HH + 255) / 256, 256>>>(W_hh, W_ih, hxs);

    // 2) Gi
    {
        dim3 grid(G3 / 128, (TT * NN) / 128);
        gi_kernel<<<grid, 256, 2 * 128 * GI_SST * 4>>>(pact);
    }

    // 3) sequential steps
    const size_t stepElems = (size_t)NN * HH;
    const size_t hASz = (size_t)NKSTG * NN * 32;
    const bool has_tail = (size_t)out_size >= (size_t)TT * stepElems + stepElems;

    dim3 grid(NSTRIP, NN / 64);                  // (16, 16) = 256 CTAs, 2/SM
    for (int tstep = 0; tstep < TT; tstep++) {
        const float* h_prev = (tstep == 0) ? hxs : out + (size_t)(tstep - 1) * stepElems;
        float* h_out  = out + (size_t)tstep * stepElems;
        float* h_out2 = (tstep == TT - 1 && has_tail) ? out + (size_t)TT * stepElems
                                                      : nullptr;
        const float* hA_cur  = hA0 + (size_t)(tstep & 1) * hASz;
        float*       hA_next = hA0 + (size_t)((tstep + 1) & 1) * hASz;
        gru_step<<<grid, NTH, SMEM_STEP>>>(
            hA_cur, hA_next, h_prev,
            masks + (size_t)tstep * NN,
            gGi + (size_t)tstep * NSTRIP * NN * 96,
            gW2, b_ih, b_hh, h_out, h_out2);
    }
}

// round 12
// speedup vs baseline: 1.4188x; 1.0911x over previous
#include <cuda_runtime.h>
#include <cuda_fp16.h>
#include <math.h>
#include <stdint.h>

// ---------------- problem dims ----------------
#define TT 128
#define NN 1024
#define HH 512
#define II 64
#define G3 1536
#define NSTRIP 16
#define NTH 256

// ---------------- device scratch ----------------
// weights: [strip][kst 0..15][96 rows][32 k]; rows cr = hgrp*24 + gate*8 + e,
// k XOR-swizzled by 8*(cr&3)
__device__ float g_Whh2[NSTRIP * 16 * 96 * 32];
__device__ float g_Wih_t[G3 * II];
__device__ float g_hA2[2][16 * NN * 32];
__device__ __half g_Gi[(size_t)TT * NSTRIP * NN * 96];  // fp16! [t][strip][n][96 cr]

// ---------------- helpers ----------------
__device__ __forceinline__ uint32_t f2tf32(float f) {
    uint32_t r;
    asm("cvt.rna.tf32.f32 %0, %1;" : "=r"(r) : "f"(f));
    return r;
}
__device__ __forceinline__ uint32_t smem_u32(const void* p) {
    uint32_t a;
    asm("{ .reg .u64 t; cvta.to.shared.u64 t, %1; cvt.u32.u64 %0, t; }" : "=r"(a) : "l"(p));
    return a;
}
__device__ __forceinline__ float sigf(float x) { return 1.0f / (1.0f + __expf(-x)); }

#define MBARRIER_INIT(addr, cnt) \
    asm volatile("mbarrier.init.shared.b64 [%0], %1;" :: "r"(addr), "r"(cnt) : "memory")
#define MBARRIER_EXPECT_TX(addr, tx) \
    asm volatile("mbarrier.arrive.expect_tx.shared.b64 _, [%0], %1;" \
                 :: "r"(addr), "r"(tx) : "memory")
#define MBARRIER_WAIT_PARITY(mbar_addr, phase_parity) do {                                 \
    uint32_t _mbar = (uint32_t)(mbar_addr);                                                \
    uint32_t _parity = (uint32_t)(phase_parity);                                           \
    uint32_t _done;                                                                        \
    asm volatile(                                                                          \
        "{\n\t.reg .pred p;\n\t"                                                           \
        "mbarrier.try_wait.parity.acquire.cta.shared::cta.b64 p, [%1], %2;\n\t"            \
        "selp.b32 %0, 1, 0, p;\n\t}"                                                       \
        : "=r"(_done) : "r"(_mbar), "r"(_parity) : "memory");                              \
    if (!_done) {                                                                          \
        asm volatile(                                                                      \
            "{\n\t.reg .pred P1;\n\t"                                                      \
            "WAIT_LOOP_%=:\n\t"                                                            \
            "mbarrier.try_wait.parity.acquire.cta.shared::cta.b64 P1, [%0], %1, 0x989680;\n\t" \
            "@P1 bra.uni WAIT_DONE_%=;\n\t"                                                \
            "bra.uni WAIT_LOOP_%=;\n\t"                                                    \
            "WAIT_DONE_%=:\n\t}"                                                           \
            :: "r"(_mbar), "r"(_parity) : "memory");                                       \
    }                                                                                      \
} while (0)

#define BULK_G2S(dst_smem, src_gmem, bytes, mbar) \
    asm volatile("cp.async.bulk.shared::cluster.global.mbarrier::complete_tx::bytes " \
                 "[%0], [%1], %2, [%3];" \
                 :: "r"(dst_smem), "l"(src_gmem), "r"(bytes), "r"(mbar) : "memory")

__device__ __forceinline__ void mma_tf32(float (&c)[4], uint32_t a0, uint32_t a1,
                                         uint32_t a2, uint32_t a3,
                                         uint32_t b0, uint32_t b1) {
    asm volatile(
        "mma.sync.aligned.m16n8k8.row.col.f32.tf32.tf32.f32 "
        "{%0,%1,%2,%3}, {%4,%5,%6,%7}, {%8,%9}, {%0,%1,%2,%3};"
        : "+f"(c[0]), "+f"(c[1]), "+f"(c[2]), "+f"(c[3])
        : "r"(a0), "r"(a1), "r"(a2), "r"(a3), "r"(b0), "r"(b1));
}

// ================= prep: cr = hgrp*24 + gate*8 + e ordering =================
__global__ void prep_kernel(const float* __restrict__ W_hh,
                            const float* __restrict__ W_ih,
                            const float* __restrict__ hxs) {
    int idx = blockIdx.x * blockDim.x + threadIdx.x;
    if (idx < G3 * HH) {
        int r = idx >> 9, k = idx & 511;
        int gg = r >> 9, u = r & 511, s = u >> 5, c = u & 31;
        int cr = (c >> 3) * 24 + gg * 8 + (c & 7);
        int kst = k >> 5, kk = k & 31;
        g_Whh2[((s * 16 + kst) * 96 + cr) * 32 + (kk ^ (8 * (cr & 3)))] =
            __uint_as_float(f2tf32(W_hh[idx]));
    }
    if (idx < G3 * II) g_Wih_t[idx] = __uint_as_float(f2tf32(W_ih[idx]));
    if (idx < NN * HH) {
        int n = idx >> 9, k = idx & 511;
        int kst = k >> 5, kk = k & 31;
        g_hA2[0][(kst * NN + n) * 32 + (kk ^ (8 * (n & 3)))] =
            __uint_as_float(f2tf32(hxs[idx]));
    }
}

// ================= Gi precompute (fp16 out, cr ordering) =================
#define GI_SST 68
__global__ __launch_bounds__(256, 1)
void gi_kernel(const float* __restrict__ X) {
    extern __shared__ float sm[];
    float* Xs = sm;
    float* Ws = sm + 128 * GI_SST;
    const int tid = threadIdx.x;
    const int rb = blockIdx.y * 128;
    const int cb = blockIdx.x * 128;

    #pragma unroll
    for (int it = 0; it < 8; it++) {
        int id = it * 256 + tid;
        int row = id >> 4, c4 = (id & 15) * 4;
        float4 v = *reinterpret_cast<const float4*>(X + (size_t)(rb + row) * II + c4);
        uint4 o = make_uint4(f2tf32(v.x), f2tf32(v.y), f2tf32(v.z), f2tf32(v.w));
        *reinterpret_cast<uint4*>(Xs + row * GI_SST + c4) = o;
        float4 w = *reinterpret_cast<const float4*>(g_Wih_t + (size_t)(cb + row) * II + c4);
        *reinterpret_cast<float4*>(Ws + row * GI_SST + c4) = w;
    }
    __syncthreads();

    const int w = tid >> 5, lane = tid & 31, g = lane >> 2, t = lane & 3;
    const int wr = w & 3, wc = w >> 2;
    float acc[2][8][4];
    #pragma unroll
    for (int sl = 0; sl < 2; sl++)
        #pragma unroll
        for (int j = 0; j < 8; j++)
            #pragma unroll
            for (int q = 0; q < 4; q++) acc[sl][j][q] = 0.0f;

    #pragma unroll
    for (int k8 = 0; k8 < 8; k8++) {
        const int kb = k8 * 8;
        uint32_t a[2][4], b[8][2];
        #pragma unroll
        for (int sl = 0; sl < 2; sl++) {
            int m0 = wr * 32 + sl * 16;
            a[sl][0] = __float_as_uint(Xs[(m0 + g) * GI_SST + kb + t]);
            a[sl][1] = __float_as_uint(Xs[(m0 + 8 + g) * GI_SST + kb + t]);
            a[sl][2] = __float_as_uint(Xs[(m0 + g) * GI_SST + kb + t + 4]);
            a[sl][3] = __float_as_uint(Xs[(m0 + 8 + g) * GI_SST + kb + t + 4]);
        }
        #pragma unroll
        for (int j = 0; j < 8; j++) {
            int n0 = wc * 64 + j * 8;
            b[j][0] = __float_as_uint(Ws[(n0 + g) * GI_SST + kb + t]);
            b[j][1] = __float_as_uint(Ws[(n0 + g) * GI_SST + kb + t + 4]);
        }
        #pragma unroll
        for (int sl = 0; sl < 2; sl++)
            #pragma unroll
            for (int j = 0; j < 8; j++)
                mma_tf32(acc[sl][j], a[sl][0], a[sl][1], a[sl][2], a[sl][3],
                         b[j][0], b[j][1]);
    }

    #pragma unroll
    for (int sl = 0; sl < 2; sl++) {
        #pragma unroll
        for (int j = 0; j < 8; j++) {
            int row = rb + wr * 32 + sl * 16 + g;
            int col = cb + wc * 64 + j * 8 + 2 * t;
            int tt = row >> 10, n = row & 1023;
            int gg = col >> 9, hcol = col & 511, s = hcol >> 5, cl = hcol & 31;
            int cr = (cl >> 3) * 24 + gg * 8 + (cl & 7);
            size_t base0 = (((size_t)tt * NSTRIP + s) * NN + n) * 96 + cr;
            *reinterpret_cast<__half2*>(&g_Gi[base0]) =
                __floats2half2_rn(acc[sl][j][0], acc[sl][j][1]);
            size_t base1 = (((size_t)tt * NSTRIP + s) * NN + (n + 8)) * 96 + cr;
            *reinterpret_cast<__half2*>(&g_Gi[base1]) =
                __floats2half2_rn(acc[sl][j][2], acc[sl][j][3]);
        }
    }
}

// ================= per-step kernel: K-stage 64, NBUF=2, fp16 Gi =================
#define NSTG 8
#define STG_B 40960                    // [A0 8K][A1 8K][B0 12K][B1 12K]
#define EPI_GI (2 * STG_B)             // 81920 : [64][96] fp16 = 12288
#define MB_OFF (EPI_GI + 12288)        // mbF[2] @0, mbGi @16
#define SMEM_STEP (MB_OFF + 64)        // 94272 -> 2 CTAs/SM

__global__ __launch_bounds__(NTH, 2)
void gru_step(const float* __restrict__ hA,      // [kst][1024][32]
              float* __restrict__ hA_next,
              const float* __restrict__ h_prev,  // fp32 [1024][512]
              const float* __restrict__ m_t,
              const __half* __restrict__ Gi_t,   // [strip][1024][96] (this t)
              const float* __restrict__ Whh2,
              const float* __restrict__ b_ih,
              const float* __restrict__ b_hh,
              float* __restrict__ h_out,
              float* __restrict__ h_out2) {
    extern __shared__ char smem[];
    const uint32_t sbase = smem_u32(smem);
    const int tid = threadIdx.x;
    const int strip = blockIdx.x;      // 0..15
    const int rb = blockIdx.y * 64;    // 0..960

    const uint32_t mbF = sbase + MB_OFF;
    const uint32_t mbGi = mbF + 16;

    const int w = tid >> 5, lane = tid & 31, g = lane >> 2, t = lane & 3;
    const int wr = w & 1, wc = w >> 1;        // 2 rowgroups(32) x 4 colgroups(24)
    const int r00 = wr * 32 + g;
    const int r10 = r00 + 16;
    const int crb = wc * 24 + g;
    const int sw0 = 8 * (g & 3);
    const int t2 = 2 * t;
    const int hc = wc * 8 + t2;

    if (tid == 0) {
        MBARRIER_INIT(mbF, 1);
        MBARRIER_INIT(mbF + 8, 1);
        MBARRIER_INIT(mbGi, 1);
    }
    __syncthreads();

    const float* Bsrc = Whh2 + (size_t)strip * 16 * 96 * 32;
    if (tid == 0) {
        #pragma unroll
        for (int s = 0; s < 2; s++) {
            MBARRIER_EXPECT_TX(mbF + 8 * s, STG_B);
            BULK_G2S(sbase + s * STG_B,         hA + ((size_t)(2 * s) * NN + rb) * 32,
                     8192, mbF + 8 * s);
            BULK_G2S(sbase + s * STG_B + 8192,  hA + ((size_t)(2 * s + 1) * NN + rb) * 32,
                     8192, mbF + 8 * s);
            BULK_G2S(sbase + s * STG_B + 16384, Bsrc + (size_t)(2 * s) * 96 * 32,
                     12288, mbF + 8 * s);
            BULK_G2S(sbase + s * STG_B + 28672, Bsrc + (size_t)(2 * s + 1) * 96 * 32,
                     12288, mbF + 8 * s);
        }
        MBARRIER_EXPECT_TX(mbGi, 12288);
        BULK_G2S(sbase + EPI_GI, Gi_t + ((size_t)strip * NN + rb) * 96, 12288, mbGi);
    }

    // ---- epilogue operand preloads (registers; overlap with mainloop) ----
    float mreg[2][2];
    float2 hpr[2][2];
    #pragma unroll
    for (int f = 0; f < 2; f++)
        #pragma unroll
        for (int rs = 0; rs < 2; rs++) {
            const int R = rb + wr * 32 + f * 16 + g + 8 * rs;
            mreg[f][rs] = m_t[R];
            hpr[f][rs] = *reinterpret_cast<const float2*>(
                &h_prev[(size_t)R * HH + strip * 32 + hc]);
        }
    const int gcol = strip * 32 + hc;
    const float2 bir = *reinterpret_cast<const float2*>(&b_ih[gcol]);
    const float2 biz = *reinterpret_cast<const float2*>(&b_ih[512 + gcol]);
    const float2 bin = *reinterpret_cast<const float2*>(&b_ih[1024 + gcol]);
    const float2 bhr = *reinterpret_cast<const float2*>(&b_hh[gcol]);
    const float2 bhz = *reinterpret_cast<const float2*>(&b_hh[512 + gcol]);
    const float2 bhn = *reinterpret_cast<const float2*>(&b_hh[1024 + gcol]);

    float acc[2][3][4];
    #pragma unroll
    for (int f = 0; f < 2; f++)
        #pragma unroll
        for (int j = 0; j < 3; j++)
            #pragma unroll
            for (int q = 0; q < 4; q++) acc[f][j][q] = 0.0f;

    // ---- mainloop: 8 big stages, NBUF=2 ----
    for (int stg = 0; stg < NSTG; stg++) {
        const int buf = stg & 1;
        MBARRIER_WAIT_PARITY(mbF + 8 * buf, (stg >> 1) & 1);
        const float* As = (const float*)(smem + buf * STG_B);
        const float* Bs = (const float*)(smem + buf * STG_B + 16384);
        #pragma unroll
        for (int k8 = 0; k8 < 8; k8++) {
            const float* Asub = As + ((k8 >= 4) ? 2048 : 0);
            const float* Bsub = Bs + ((k8 >= 4) ? 3072 : 0);
            const int koff = ((k8 & 3) * 8 + t2) ^ sw0;
            float2 a00 = *reinterpret_cast<const float2*>(&Asub[r00 * 32 + koff]);
            float2 a01 = *reinterpret_cast<const float2*>(&Asub[(r00 + 8) * 32 + koff]);
            float2 a10 = *reinterpret_cast<const float2*>(&Asub[r10 * 32 + koff]);
            float2 a11 = *reinterpret_cast<const float2*>(&Asub[(r10 + 8) * 32 + koff]);
            float2 b0 = *reinterpret_cast<const float2*>(&Bsub[crb * 32 + koff]);
            float2 b1 = *reinterpret_cast<const float2*>(&Bsub[(crb + 8) * 32 + koff]);
            float2 b2 = *reinterpret_cast<const float2*>(&Bsub[(crb + 16) * 32 + koff]);
            mma_tf32(acc[0][0], __float_as_uint(a00.x), __float_as_uint(a01.x),
                     __float_as_uint(a00.y), __float_as_uint(a01.y),
                     __float_as_uint(b0.x), __float_as_uint(b0.y));
            mma_tf32(acc[0][1], __float_as_uint(a00.x), __float_as_uint(a01.x),
                     __float_as_uint(a00.y), __float_as_uint(a01.y),
                     __float_as_uint(b1.x), __float_as_uint(b1.y));
            mma_tf32(acc[0][2], __float_as_uint(a00.x), __float_as_uint(a01.x),
                     __float_as_uint(a00.y), __float_as_uint(a01.y),
                     __float_as_uint(b2.x), __float_as_uint(b2.y));
            mma_tf32(acc[1][0], __float_as_uint(a10.x), __float_as_uint(a11.x),
                     __float_as_uint(a10.y), __float_as_uint(a11.y),
                     __float_as_uint(b0.x), __float_as_uint(b0.y));
            mma_tf32(acc[1][1], __float_as_uint(a10.x), __float_as_uint(a11.x),
                     __float_as_uint(a10.y), __float_as_uint(a11.y),
                     __float_as_uint(b1.x), __float_as_uint(b1.y));
            mma_tf32(acc[1][2], __float_as_uint(a10.x), __float_as_uint(a11.x),
                     __float_as_uint(a10.y), __float_as_uint(a11.y),
                     __float_as_uint(b2.x), __float_as_uint(b2.y));
        }
        __syncthreads();
        if (tid == 0 && stg + 2 < NSTG) {
            const int s2 = stg + 2;
            MBARRIER_EXPECT_TX(mbF + 8 * buf, STG_B);
            BULK_G2S(sbase + buf * STG_B,         hA + ((size_t)(2 * s2) * NN + rb) * 32,
                     8192, mbF + 8 * buf);
            BULK_G2S(sbase + buf * STG_B + 8192,  hA + ((size_t)(2 * s2 + 1) * NN + rb) * 32,
                     8192, mbF + 8 * buf);
            BULK_G2S(sbase + buf * STG_B + 16384, Bsrc + (size_t)(2 * s2) * 96 * 32,
                     12288, mbF + 8 * buf);
            BULK_G2S(sbase + buf * STG_B + 28672, Bsrc + (size_t)(2 * s2 + 1) * 96 * 32,
                     12288, mbF + 8 * buf);
        }
    }

    // ---- fragment-direct epilogue (fp16 Gi) ----
    MBARRIER_WAIT_PARITY(mbGi, 0);
    const __half* sGi = (const __half*)(smem + EPI_GI);

    #pragma unroll
    for (int f = 0; f < 2; f++) {
        #pragma unroll
        for (int rs = 0; rs < 2; rs++) {
            const int Rl = wr * 32 + f * 16 + g + 8 * rs;
            const int R = rb + Rl;
            const float m = mreg[f][rs];
            const float2 gr = __half22float2(*reinterpret_cast<const __half2*>(
                &sGi[Rl * 96 + wc * 24 + t2]));
            const float2 gz = __half22float2(*reinterpret_cast<const __half2*>(
                &sGi[Rl * 96 + wc * 24 + 8 + t2]));
            const float2 gn = __half22float2(*reinterpret_cast<const __half2*>(
                &sGi[Rl * 96 + wc * 24 + 16 + t2]));
            const float sr0 = acc[f][0][2 * rs], sr1 = acc[f][0][2 * rs + 1];
            const float sz0 = acc[f][1][2 * rs], sz1 = acc[f][1][2 * rs + 1];
            const float sn0 = acc[f][2][2 * rs], sn1 = acc[f][2][2 * rs + 1];
            const float2 hp = hpr[f][rs];

            float rv0 = sigf(fmaf(m, sr0 + gr.x, bir.x + bhr.x));
            float rv1 = sigf(fmaf(m, sr1 + gr.y, bir.y + bhr.y));
            float zv0 = sigf(fmaf(m, sz0 + gz.x, biz.x + bhz.x));
            float zv1 = sigf(fmaf(m, sz1 + gz.y, biz.y + bhz.y));
            float nv0 = tanhf(fmaf(m, gn.x, bin.x) + rv0 * fmaf(m, sn0, bhn.x));
            float nv1 = tanhf(fmaf(m, gn.y, bin.y) + rv1 * fmaf(m, sn1, bhn.y));
            float h0 = fmaf(zv0, fmaf(m, hp.x, -nv0), nv0);
            float h1 = fmaf(zv1, fmaf(m, hp.y, -nv1), nv1);

            *reinterpret_cast<float2*>(&h_out[(size_t)R * HH + gcol]) =
                make_float2(h0, h1);
            if (h_out2)
                *reinterpret_cast<float2*>(&h_out2[(size_t)R * HH + gcol]) =
                    make_float2(h0, h1);
            uint2 oc = make_uint2(f2tf32(h0), f2tf32(h1));
            *reinterpret_cast<uint2*>(
                &hA_next[((size_t)strip * NN + R) * 32 + (hc ^ (8 * (R & 3)))]) = oc;
        }
    }
}

// ---------------- host ----------------
extern "C" void kernel_launch(void* const* d_in, const int* in_sizes, int n_in,
                              void* d_out, int out_size) {
    const float* hxs   = (const float*)d_in[0];
    const float* masks = (const float*)d_in[2];
    const float* pact  = (const float*)d_in[3];
    const float* W_ih  = (const float*)d_in[4];
    const float* W_hh  = (const float*)d_in[5];
    const float* b_ih  = (const float*)d_in[6];
    const float* b_hh  = (const float*)d_in[7];
    float* out = (float*)d_out;

    static bool attr_set = false;
    if (!attr_set) {
        cudaFuncSetAttribute(gi_kernel, cudaFuncAttributeMaxDynamicSharedMemorySize,
                             2 * 128 * GI_SST * 4);
        cudaFuncSetAttribute(gru_step, cudaFuncAttributeMaxDynamicSharedMemorySize,
                             SMEM_STEP);
        attr_set = true;
    }

    static float* hA0 = nullptr;
    static __half* gGi = nullptr;
    static float* gW2 = nullptr;
    if (!hA0) cudaGetSymbolAddress((void**)&hA0, g_hA2);
    if (!gGi) cudaGetSymbolAddress((void**)&gGi, g_Gi);
    if (!gW2) cudaGetSymbolAddress((void**)&gW2, g_Whh2);

    // 1) prep
    prep_kernel<<<(G3 * HH + 255) / 256, 256>>>(W_hh, W_ih, hxs);

    // 2) Gi (fp16 output)
    {
        dim3 grid(G3 / 128, (TT * NN) / 128);
        gi_kernel<<<grid, 256, 2 * 128 * GI_SST * 4>>>(pact);
    }

    // 3) sequential steps
    const size_t stepElems = (size_t)NN * HH;
    const size_t hASz = (size_t)16 * NN * 32;
    const bool has_tail = (size_t)out_size >= (size_t)TT * stepElems + stepElems;

    dim3 grid(NSTRIP, NN / 64);                  // (16, 16) = 256 CTAs, 2/SM
    for (int tstep = 0; tstep < TT; tstep++) {
        const float* h_prev = (tstep == 0) ? hxs : out + (size_t)(tstep - 1) * stepElems;
        float* h_out  = out + (size_t)tstep * stepElems;
        float* h_out2 = (tstep == TT - 1 && has_tail) ? out + (size_t)TT * stepElems
                                                      : nullptr;
        const float* hA_cur  = hA0 + (size_t)(tstep & 1) * hASz;
        float*       hA_next = hA0 + (size_t)((tstep + 1) & 1) * hASz;
        gru_step<<<grid, NTH, SMEM_STEP>>>(
            hA_cur, hA_next, h_prev,
            masks + (size_t)tstep * NN,
            gGi + (size_t)tstep * NSTRIP * NN * 96,
            gW2, b_ih, b_hh, h_out, h_out2);
    }
}

// round 13
// speedup vs baseline: 1.9014x; 1.3402x over previous
#include <cuda_runtime.h>
#include <cuda_fp16.h>
#include <math.h>
#include <stdint.h>

// ---------------- problem dims ----------------
#define TT 128
#define NN 1024
#define HH 512
#define II 64
#define G3 1536
#define NSTRIP 16
#define NTH 256

// ---------------- device scratch ----------------
// weights fp16: [strip][kst64 0..7][96 rows][64 k]; rows cr = hgrp*24+gate*8+e,
// k XOR-swizzled by 16*(cr&3) (halves)
__device__ __half g_Whh2h[NSTRIP * 8 * 96 * 64];
__device__ float  g_Wih_t[G3 * II];
__device__ __half g_hA2h[2][8 * NN * 64];               // fp16 h ping-pong
__device__ __half g_Gi[(size_t)TT * NSTRIP * NN * 96];  // fp16 [t][strip][n][96 cr]

// ---------------- helpers ----------------
__device__ __forceinline__ uint32_t f2tf32(float f) {
    uint32_t r;
    asm("cvt.rna.tf32.f32 %0, %1;" : "=r"(r) : "f"(f));
    return r;
}
__device__ __forceinline__ uint32_t smem_u32(const void* p) {
    uint32_t a;
    asm("{ .reg .u64 t; cvta.to.shared.u64 t, %1; cvt.u32.u64 %0, t; }" : "=r"(a) : "l"(p));
    return a;
}
__device__ __forceinline__ float sigf(float x) { return 1.0f / (1.0f + __expf(-x)); }

#define MBARRIER_INIT(addr, cnt) \
    asm volatile("mbarrier.init.shared.b64 [%0], %1;" :: "r"(addr), "r"(cnt) : "memory")
#define MBARRIER_EXPECT_TX(addr, tx) \
    asm volatile("mbarrier.arrive.expect_tx.shared.b64 _, [%0], %1;" \
                 :: "r"(addr), "r"(tx) : "memory")
#define MBARRIER_WAIT_PARITY(mbar_addr, phase_parity) do {                                 \
    uint32_t _mbar = (uint32_t)(mbar_addr);                                                \
    uint32_t _parity = (uint32_t)(phase_parity);                                           \
    uint32_t _done;                                                                        \
    asm volatile(                                                                          \
        "{\n\t.reg .pred p;\n\t"                                                           \
        "mbarrier.try_wait.parity.acquire.cta.shared::cta.b64 p, [%1], %2;\n\t"            \
        "selp.b32 %0, 1, 0, p;\n\t}"                                                       \
        : "=r"(_done) : "r"(_mbar), "r"(_parity) : "memory");                              \
    if (!_done) {                                                                          \
        asm volatile(                                                                      \
            "{\n\t.reg .pred P1;\n\t"                                                      \
            "WAIT_LOOP_%=:\n\t"                                                            \
            "mbarrier.try_wait.parity.acquire.cta.shared::cta.b64 P1, [%0], %1, 0x989680;\n\t" \
            "@P1 bra.uni WAIT_DONE_%=;\n\t"                                                \
            "bra.uni WAIT_LOOP_%=;\n\t"                                                    \
            "WAIT_DONE_%=:\n\t}"                                                           \
            :: "r"(_mbar), "r"(_parity) : "memory");                                       \
    }                                                                                      \
} while (0)

#define BULK_G2S(dst_smem, src_gmem, bytes, mbar) \
    asm volatile("cp.async.bulk.shared::cluster.global.mbarrier::complete_tx::bytes " \
                 "[%0], [%1], %2, [%3];" \
                 :: "r"(dst_smem), "l"(src_gmem), "r"(bytes), "r"(mbar) : "memory")

__device__ __forceinline__ void mma_tf32(float (&c)[4], uint32_t a0, uint32_t a1,
                                         uint32_t a2, uint32_t a3,
                                         uint32_t b0, uint32_t b1) {
    asm volatile(
        "mma.sync.aligned.m16n8k8.row.col.f32.tf32.tf32.f32 "
        "{%0,%1,%2,%3}, {%4,%5,%6,%7}, {%8,%9}, {%0,%1,%2,%3};"
        : "+f"(c[0]), "+f"(c[1]), "+f"(c[2]), "+f"(c[3])
        : "r"(a0), "r"(a1), "r"(a2), "r"(a3), "r"(b0), "r"(b1));
}
__device__ __forceinline__ void mma_f16(float (&c)[4], uint32_t a0, uint32_t a1,
                                        uint32_t a2, uint32_t a3,
                                        uint32_t b0, uint32_t b1) {
    asm volatile(
        "mma.sync.aligned.m16n8k16.row.col.f32.f16.f16.f32 "
        "{%0,%1,%2,%3}, {%4,%5,%6,%7}, {%8,%9}, {%0,%1,%2,%3};"
        : "+f"(c[0]), "+f"(c[1]), "+f"(c[2]), "+f"(c[3])
        : "r"(a0), "r"(a1), "r"(a2), "r"(a3), "r"(b0), "r"(b1));
}

// ================= prep: fp16 weights/h with 128B-row swizzle =================
__global__ void prep_kernel(const float* __restrict__ W_hh,
                            const float* __restrict__ W_ih,
                            const float* __restrict__ hxs) {
    int idx = blockIdx.x * blockDim.x + threadIdx.x;
    if (idx < G3 * HH) {
        int r = idx >> 9, k = idx & 511;
        int gg = r >> 9, u = r & 511, s = u >> 5, c = u & 31;
        int cr = (c >> 3) * 24 + gg * 8 + (c & 7);
        int kst = k >> 6, kk = k & 63;
        g_Whh2h[((s * 8 + kst) * 96 + cr) * 64 + (kk ^ (16 * (cr & 3)))] =
            __float2half_rn(W_hh[idx]);
    }
    if (idx < G3 * II) g_Wih_t[idx] = __uint_as_float(f2tf32(W_ih[idx]));
    if (idx < NN * HH) {
        int n = idx >> 9, k = idx & 511;
        int kst = k >> 6, kk = k & 63;
        g_hA2h[0][(kst * NN + n) * 64 + (kk ^ (16 * (n & 3)))] =
            __float2half_rn(hxs[idx]);
    }
}

// ================= Gi precompute (tf32 math, fp16 out, cr ordering) ==========
#define GI_SST 68
__global__ __launch_bounds__(256, 1)
void gi_kernel(const float* __restrict__ X) {
    extern __shared__ float sm[];
    float* Xs = sm;
    float* Ws = sm + 128 * GI_SST;
    const int tid = threadIdx.x;
    const int rb = blockIdx.y * 128;
    const int cb = blockIdx.x * 128;

    #pragma unroll
    for (int it = 0; it < 8; it++) {
        int id = it * 256 + tid;
        int row = id >> 4, c4 = (id & 15) * 4;
        float4 v = *reinterpret_cast<const float4*>(X + (size_t)(rb + row) * II + c4);
        uint4 o = make_uint4(f2tf32(v.x), f2tf32(v.y), f2tf32(v.z), f2tf32(v.w));
        *reinterpret_cast<uint4*>(Xs + row * GI_SST + c4) = o;
        float4 w = *reinterpret_cast<const float4*>(g_Wih_t + (size_t)(cb + row) * II + c4);
        *reinterpret_cast<float4*>(Ws + row * GI_SST + c4) = w;
    }
    __syncthreads();

    const int w = tid >> 5, lane = tid & 31, g = lane >> 2, t = lane & 3;
    const int wr = w & 3, wc = w >> 2;
    float acc[2][8][4];
    #pragma unroll
    for (int sl = 0; sl < 2; sl++)
        #pragma unroll
        for (int j = 0; j < 8; j++)
            #pragma unroll
            for (int q = 0; q < 4; q++) acc[sl][j][q] = 0.0f;

    #pragma unroll
    for (int k8 = 0; k8 < 8; k8++) {
        const int kb = k8 * 8;
        uint32_t a[2][4], b[8][2];
        #pragma unroll
        for (int sl = 0; sl < 2; sl++) {
            int m0 = wr * 32 + sl * 16;
            a[sl][0] = __float_as_uint(Xs[(m0 + g) * GI_SST + kb + t]);
            a[sl][1] = __float_as_uint(Xs[(m0 + 8 + g) * GI_SST + kb + t]);
            a[sl][2] = __float_as_uint(Xs[(m0 + g) * GI_SST + kb + t + 4]);
            a[sl][3] = __float_as_uint(Xs[(m0 + 8 + g) * GI_SST + kb + t + 4]);
        }
        #pragma unroll
        for (int j = 0; j < 8; j++) {
            int n0 = wc * 64 + j * 8;
            b[j][0] = __float_as_uint(Ws[(n0 + g) * GI_SST + kb + t]);
            b[j][1] = __float_as_uint(Ws[(n0 + g) * GI_SST + kb + t + 4]);
        }
        #pragma unroll
        for (int sl = 0; sl < 2; sl++)
            #pragma unroll
            for (int j = 0; j < 8; j++)
                mma_tf32(acc[sl][j], a[sl][0], a[sl][1], a[sl][2], a[sl][3],
                         b[j][0], b[j][1]);
    }

    #pragma unroll
    for (int sl = 0; sl < 2; sl++) {
        #pragma unroll
        for (int j = 0; j < 8; j++) {
            int row = rb + wr * 32 + sl * 16 + g;
            int col = cb + wc * 64 + j * 8 + 2 * t;
            int tt = row >> 10, n = row & 1023;
            int gg = col >> 9, hcol = col & 511, s = hcol >> 5, cl = hcol & 31;
            int cr = (cl >> 3) * 24 + gg * 8 + (cl & 7);
            size_t base0 = (((size_t)tt * NSTRIP + s) * NN + n) * 96 + cr;
            *reinterpret_cast<__half2*>(&g_Gi[base0]) =
                __floats2half2_rn(acc[sl][j][0], acc[sl][j][1]);
            size_t base1 = (((size_t)tt * NSTRIP + s) * NN + (n + 8)) * 96 + cr;
            *reinterpret_cast<__half2*>(&g_Gi[base1]) =
                __floats2half2_rn(acc[sl][j][2], acc[sl][j][3]);
        }
    }
}

// ================= per-step kernel: fp16 m16n8k16, K-stage 64 =================
#define NSTG 8
#define A_STG_B 8192                   // 64 rows x 64 halves x 2
#define B_STG_B 12288                  // 96 rows x 64 halves x 2
#define STG_B (A_STG_B + B_STG_B)      // 20480
#define EPI_GI (2 * STG_B)             // 40960 : [64][96] fp16 = 12288
#define MB_OFF (EPI_GI + 12288)
#define SMEM_STEP (MB_OFF + 64)        // ~53.3 KB

__global__ __launch_bounds__(NTH, 2)
void gru_step(const __half* __restrict__ hA,     // [kst64][1024][64] swizzled
              __half* __restrict__ hA_next,
              const float* __restrict__ h_prev,  // fp32 [1024][512]
              const float* __restrict__ m_t,
              const __half* __restrict__ Gi_t,   // [strip][1024][96] (this t)
              const __half* __restrict__ Whh2,
              const float* __restrict__ b_ih,
              const float* __restrict__ b_hh,
              float* __restrict__ h_out,
              float* __restrict__ h_out2) {
    extern __shared__ char smem[];
    const uint32_t sbase = smem_u32(smem);
    const int tid = threadIdx.x;
    const int strip = blockIdx.x;      // 0..15
    const int rb = blockIdx.y * 64;    // 0..960

    const uint32_t mbF = sbase + MB_OFF;
    const uint32_t mbGi = mbF + 16;

    const int w = tid >> 5, lane = tid & 31, g = lane >> 2, t = lane & 3;
    const int wr = w & 1, wc = w >> 1;        // 2 rowgroups(32) x 4 colgroups(24)
    const int r00 = wr * 32 + g;
    const int r10 = r00 + 16;
    const int crb = wc * 24 + g;
    const int g3m = g & 3;
    const int t2 = 2 * t;
    const int hc = wc * 8 + t2;

    if (tid == 0) {
        MBARRIER_INIT(mbF, 1);
        MBARRIER_INIT(mbF + 8, 1);
        MBARRIER_INIT(mbGi, 1);
    }
    __syncthreads();

    const __half* Bsrc = Whh2 + (size_t)strip * 8 * 96 * 64;
    if (tid == 0) {
        #pragma unroll
        for (int s = 0; s < 2; s++) {
            MBARRIER_EXPECT_TX(mbF + 8 * s, STG_B);
            BULK_G2S(sbase + s * STG_B, hA + ((size_t)s * NN + rb) * 64,
                     A_STG_B, mbF + 8 * s);
            BULK_G2S(sbase + s * STG_B + A_STG_B, Bsrc + (size_t)s * 96 * 64,
                     B_STG_B, mbF + 8 * s);
        }
        MBARRIER_EXPECT_TX(mbGi, 12288);
        BULK_G2S(sbase + EPI_GI, Gi_t + ((size_t)strip * NN + rb) * 96, 12288, mbGi);
    }

    // ---- epilogue operand preloads ----
    float mreg[2][2];
    float2 hpr[2][2];
    #pragma unroll
    for (int f = 0; f < 2; f++)
        #pragma unroll
        for (int rs = 0; rs < 2; rs++) {
            const int R = rb + wr * 32 + f * 16 + g + 8 * rs;
            mreg[f][rs] = m_t[R];
            hpr[f][rs] = *reinterpret_cast<const float2*>(
                &h_prev[(size_t)R * HH + strip * 32 + hc]);
        }
    const int gcol = strip * 32 + hc;
    const float2 bir = *reinterpret_cast<const float2*>(&b_ih[gcol]);
    const float2 biz = *reinterpret_cast<const float2*>(&b_ih[512 + gcol]);
    const float2 bin = *reinterpret_cast<const float2*>(&b_ih[1024 + gcol]);
    const float2 bhr = *reinterpret_cast<const float2*>(&b_hh[gcol]);
    const float2 bhz = *reinterpret_cast<const float2*>(&b_hh[512 + gcol]);
    const float2 bhn = *reinterpret_cast<const float2*>(&b_hh[1024 + gcol]);

    float acc[2][3][4];
    #pragma unroll
    for (int f = 0; f < 2; f++)
        #pragma unroll
        for (int j = 0; j < 3; j++)
            #pragma unroll
            for (int q = 0; q < 4; q++) acc[f][j][q] = 0.0f;

    // ---- mainloop: 8 k64 stages, NBUF=2, fp16 m16n8k16 ----
    for (int stg = 0; stg < NSTG; stg++) {
        const int buf = stg & 1;
        MBARRIER_WAIT_PARITY(mbF + 8 * buf, (stg >> 1) & 1);
        const __half* As = (const __half*)(smem + buf * STG_B);
        const __half* Bs = (const __half*)(smem + buf * STG_B + A_STG_B);
        #pragma unroll
        for (int c = 0; c < 4; c++) {
            // swizzled halves offset: ((c ^ (g&3))*16 + 4t); 4 consecutive halves
            const int koff = ((c ^ g3m) * 16) + 4 * t;
            uint2 a00 = *reinterpret_cast<const uint2*>(&As[r00 * 64 + koff]);
            uint2 a01 = *reinterpret_cast<const uint2*>(&As[(r00 + 8) * 64 + koff]);
            uint2 a10 = *reinterpret_cast<const uint2*>(&As[r10 * 64 + koff]);
            uint2 a11 = *reinterpret_cast<const uint2*>(&As[(r10 + 8) * 64 + koff]);
            uint2 b0 = *reinterpret_cast<const uint2*>(&Bs[crb * 64 + koff]);
            uint2 b1 = *reinterpret_cast<const uint2*>(&Bs[(crb + 8) * 64 + koff]);
            uint2 b2 = *reinterpret_cast<const uint2*>(&Bs[(crb + 16) * 64 + koff]);
            mma_f16(acc[0][0], a00.x, a01.x, a00.y, a01.y, b0.x, b0.y);
            mma_f16(acc[0][1], a00.x, a01.x, a00.y, a01.y, b1.x, b1.y);
            mma_f16(acc[0][2], a00.x, a01.x, a00.y, a01.y, b2.x, b2.y);
            mma_f16(acc[1][0], a10.x, a11.x, a10.y, a11.y, b0.x, b0.y);
            mma_f16(acc[1][1], a10.x, a11.x, a10.y, a11.y, b1.x, b1.y);
            mma_f16(acc[1][2], a10.x, a11.x, a10.y, a11.y, b2.x, b2.y);
        }
        __syncthreads();
        if (tid == 0 && stg + 2 < NSTG) {
            const int s2 = stg + 2;
            MBARRIER_EXPECT_TX(mbF + 8 * buf, STG_B);
            BULK_G2S(sbase + buf * STG_B, hA + ((size_t)s2 * NN + rb) * 64,
                     A_STG_B, mbF + 8 * buf);
            BULK_G2S(sbase + buf * STG_B + A_STG_B, Bsrc + (size_t)s2 * 96 * 64,
                     B_STG_B, mbF + 8 * buf);
        }
    }

    // ---- fragment-direct epilogue (fp16 Gi) ----
    MBARRIER_WAIT_PARITY(mbGi, 0);
    const __half* sGi = (const __half*)(smem + EPI_GI);
    const int kstO = strip >> 1;
    const int khO = (strip & 1) * 32 + hc;

    #pragma unroll
    for (int f = 0; f < 2; f++) {
        #pragma unroll
        for (int rs = 0; rs < 2; rs++) {
            const int Rl = wr * 32 + f * 16 + g + 8 * rs;
            const int R = rb + Rl;
            const float m = mreg[f][rs];
            const float2 gr = __half22float2(*reinterpret_cast<const __half2*>(
                &sGi[Rl * 96 + wc * 24 + t2]));
            const float2 gz = __half22float2(*reinterpret_cast<const __half2*>(
                &sGi[Rl * 96 + wc * 24 + 8 + t2]));
            const float2 gn = __half22float2(*reinterpret_cast<const __half2*>(
                &sGi[Rl * 96 + wc * 24 + 16 + t2]));
            const float sr0 = acc[f][0][2 * rs], sr1 = acc[f][0][2 * rs + 1];
            const float sz0 = acc[f][1][2 * rs], sz1 = acc[f][1][2 * rs + 1];
            const float sn0 = acc[f][2][2 * rs], sn1 = acc[f][2][2 * rs + 1];
            const float2 hp = hpr[f][rs];

            float rv0 = sigf(fmaf(m, sr0 + gr.x, bir.x + bhr.x));
            float rv1 = sigf(fmaf(m, sr1 + gr.y, bir.y + bhr.y));
            float zv0 = sigf(fmaf(m, sz0 + gz.x, biz.x + bhz.x));
            float zv1 = sigf(fmaf(m, sz1 + gz.y, biz.y + bhz.y));
            float nv0 = tanhf(fmaf(m, gn.x, bin.x) + rv0 * fmaf(m, sn0, bhn.x));
            float nv1 = tanhf(fmaf(m, gn.y, bin.y) + rv1 * fmaf(m, sn1, bhn.y));
            float h0 = fmaf(zv0, fmaf(m, hp.x, -nv0), nv0);
            float h1 = fmaf(zv1, fmaf(m, hp.y, -nv1), nv1);

            *reinterpret_cast<float2*>(&h_out[(size_t)R * HH + gcol]) =
                make_float2(h0, h1);
            if (h_out2)
                *reinterpret_cast<float2*>(&h_out2[(size_t)R * HH + gcol]) =
                    make_float2(h0, h1);
            __half2 oc = __floats2half2_rn(h0, h1);
            *reinterpret_cast<__half2*>(
                &hA_next[((size_t)kstO * NN + R) * 64 + (khO ^ (16 * (R & 3)))]) = oc;
        }
    }
}

// ---------------- host ----------------
extern "C" void kernel_launch(void* const* d_in, const int* in_sizes, int n_in,
                              void* d_out, int out_size) {
    const float* hxs   = (const float*)d_in[0];
    const float* masks = (const float*)d_in[2];
    const float* pact  = (const float*)d_in[3];
    const float* W_ih  = (const float*)d_in[4];
    const float* W_hh  = (const float*)d_in[5];
    const float* b_ih  = (const float*)d_in[6];
    const float* b_hh  = (const float*)d_in[7];
    float* out = (float*)d_out;

    static bool attr_set = false;
    if (!attr_set) {
        cudaFuncSetAttribute(gi_kernel, cudaFuncAttributeMaxDynamicSharedMemorySize,
                             2 * 128 * GI_SST * 4);
        cudaFuncSetAttribute(gru_step, cudaFuncAttributeMaxDynamicSharedMemorySize,
                             SMEM_STEP);
        attr_set = true;
    }

    static __half* hA0 = nullptr;
    static __half* gGi = nullptr;
    static __half* gW2 = nullptr;
    if (!hA0) cudaGetSymbolAddress((void**)&hA0, g_hA2h);
    if (!gGi) cudaGetSymbolAddress((void**)&gGi, g_Gi);
    if (!gW2) cudaGetSymbolAddress((void**)&gW2, g_Whh2h);

    // 1) prep
    prep_kernel<<<(G3 * HH + 255) / 256, 256>>>(W_hh, W_ih, hxs);

    // 2) Gi (fp16 output)
    {
        dim3 grid(G3 / 128, (TT * NN) / 128);
        gi_kernel<<<grid, 256, 2 * 128 * GI_SST * 4>>>(pact);
    }

    // 3) sequential steps
    const size_t stepElems = (size_t)NN * HH;
    const size_t hASz = (size_t)8 * NN * 64;
    const bool has_tail = (size_t)out_size >= (size_t)TT * stepElems + stepElems;

    dim3 grid(NSTRIP, NN / 64);                  // (16, 16) = 256 CTAs, 2/SM
    for (int tstep = 0; tstep < TT; tstep++) {
        const float* h_prev = (tstep == 0) ? hxs : out + (size_t)(tstep - 1) * stepElems;
        float* h_out  = out + (size_t)tstep * stepElems;
        float* h_out2 = (tstep == TT - 1 && has_tail) ? out + (size_t)TT * stepElems
                                                      : nullptr;
        const __half* hA_cur  = hA0 + (size_t)(tstep & 1) * hASz;
        __half*       hA_next = hA0 + (size_t)((tstep + 1) & 1) * hASz;
        gru_step<<<grid, NTH, SMEM_STEP>>>(
            hA_cur, hA_next, h_prev,
            masks + (size_t)tstep * NN,
            gGi + (size_t)tstep * NSTRIP * NN * 96,
            gW2, b_ih, b_hh, h_out, h_out2);
    }
}

// round 14
// speedup vs baseline: 2.4198x; 1.2726x over previous
#include <cuda_runtime.h>
#include <cuda_fp16.h>
#include <math.h>
#include <stdint.h>

// ---------------- problem dims ----------------
#define TT 128
#define NN 1024
#define HH 512
#define II 64
#define G3 1536
#define NSTRIP 16
#define NTH 256

// ---------------- device scratch ----------------
// W_hh fp16: [strip][kst64 0..7][96 rows][64 k]; rows cr = hgrp*24+gate*8+e,
// k XOR-swizzled by 16*(cr&3) (halves)
__device__ __half g_Whh2h[NSTRIP * 8 * 96 * 64];
// W_ih fp16: [strip][96 rows][64 k], same cr ordering/swizzle
__device__ __half g_Wih_h[NSTRIP * 96 * 64];
// X fp16: [t][n][64], swizzled by 16*(n&3)
__device__ __half g_Xh[(size_t)TT * NN * II];
__device__ __half g_hA2h[2][8 * NN * 64];               // fp16 h ping-pong

// ---------------- helpers ----------------
__device__ __forceinline__ uint32_t smem_u32(const void* p) {
    uint32_t a;
    asm("{ .reg .u64 t; cvta.to.shared.u64 t, %1; cvt.u32.u64 %0, t; }" : "=r"(a) : "l"(p));
    return a;
}
__device__ __forceinline__ float sigf(float x) { return 1.0f / (1.0f + __expf(-x)); }

#define MBARRIER_INIT(addr, cnt) \
    asm volatile("mbarrier.init.shared.b64 [%0], %1;" :: "r"(addr), "r"(cnt) : "memory")
#define MBARRIER_EXPECT_TX(addr, tx) \
    asm volatile("mbarrier.arrive.expect_tx.shared.b64 _, [%0], %1;" \
                 :: "r"(addr), "r"(tx) : "memory")
#define MBARRIER_WAIT_PARITY(mbar_addr, phase_parity) do {                                 \
    uint32_t _mbar = (uint32_t)(mbar_addr);                                                \
    uint32_t _parity = (uint32_t)(phase_parity);                                           \
    uint32_t _done;                                                                        \
    asm volatile(                                                                          \
        "{\n\t.reg .pred p;\n\t"                                                           \
        "mbarrier.try_wait.parity.acquire.cta.shared::cta.b64 p, [%1], %2;\n\t"            \
        "selp.b32 %0, 1, 0, p;\n\t}"                                                       \
        : "=r"(_done) : "r"(_mbar), "r"(_parity) : "memory");                              \
    if (!_done) {                                                                          \
        asm volatile(                                                                      \
            "{\n\t.reg .pred P1;\n\t"                                                      \
            "WAIT_LOOP_%=:\n\t"                                                            \
            "mbarrier.try_wait.parity.acquire.cta.shared::cta.b64 P1, [%0], %1, 0x989680;\n\t" \
            "@P1 bra.uni WAIT_DONE_%=;\n\t"                                                \
            "bra.uni WAIT_LOOP_%=;\n\t"                                                    \
            "WAIT_DONE_%=:\n\t}"                                                           \
            :: "r"(_mbar), "r"(_parity) : "memory");                                       \
    }                                                                                      \
} while (0)

#define BULK_G2S(dst_smem, src_gmem, bytes, mbar) \
    asm volatile("cp.async.bulk.shared::cluster.global.mbarrier::complete_tx::bytes " \
                 "[%0], [%1], %2, [%3];" \
                 :: "r"(dst_smem), "l"(src_gmem), "r"(bytes), "r"(mbar) : "memory")

__device__ __forceinline__ void mma_f16(float (&c)[4], uint32_t a0, uint32_t a1,
                                        uint32_t a2, uint32_t a3,
                                        uint32_t b0, uint32_t b1) {
    asm volatile(
        "mma.sync.aligned.m16n8k16.row.col.f32.f16.f16.f32 "
        "{%0,%1,%2,%3}, {%4,%5,%6,%7}, {%8,%9}, {%0,%1,%2,%3};"
        : "+f"(c[0]), "+f"(c[1]), "+f"(c[2]), "+f"(c[3])
        : "r"(a0), "r"(a1), "r"(a2), "r"(a3), "r"(b0), "r"(b1));
}

// ================= prep: all fp16 layouts =================
__global__ void prep_kernel(const float* __restrict__ W_hh,
                            const float* __restrict__ W_ih,
                            const float* __restrict__ hxs,
                            const float* __restrict__ X) {
    int idx = blockIdx.x * blockDim.x + threadIdx.x;
    if (idx < G3 * HH) {                 // W_hh[r][k], k 0..511
        int r = idx >> 9, k = idx & 511;
        int gg = r >> 9, u = r & 511, s = u >> 5, c = u & 31;
        int cr = (c >> 3) * 24 + gg * 8 + (c & 7);
        int kst = k >> 6, kk = k & 63;
        g_Whh2h[((s * 8 + kst) * 96 + cr) * 64 + (kk ^ (16 * (cr & 3)))] =
            __float2half_rn(W_hh[idx]);
    }
    if (idx < G3 * II) {                 // W_ih[r][k], k 0..63
        int r = idx >> 6, k = idx & 63;
        int gg = r >> 9, u = r & 511, s = u >> 5, c = u & 31;
        int cr = (c >> 3) * 24 + gg * 8 + (c & 7);
        g_Wih_h[(s * 96 + cr) * 64 + (k ^ (16 * (cr & 3)))] = __float2half_rn(W_ih[idx]);
    }
    if (idx < NN * HH) {                 // hxs -> hA ping 0
        int n = idx >> 9, k = idx & 511;
        int kst = k >> 6, kk = k & 63;
        g_hA2h[0][(kst * NN + n) * 64 + (kk ^ (16 * (n & 3)))] =
            __float2half_rn(hxs[idx]);
    }
    if (idx < TT * NN * II) {            // X -> fp16 swizzled
        int tn = idx >> 6, k = idx & 63;
        int n = tn & 1023;
        g_Xh[(size_t)tn * 64 + (k ^ (16 * (n & 3)))] = __float2half_rn(X[idx]);
    }
}

// ================= per-step kernel: fused x-stage + 4 K128 h-stages ============
#define XW_OFF 0                        // x 8 KB @0, Wih 12 KB @8192
#define HSTG 20480                      // 2 x 40960 h-stage buffers
#define MB_OFF (HSTG + 2 * 40960)       // mbX @0, mbF0 @8, mbF1 @16
#define SMEM_STEP (MB_OFF + 64)         // 102464 -> 2 CTAs/SM

__global__ __launch_bounds__(NTH, 2)
void gru_step(const __half* __restrict__ hA,     // [kst64][1024][64] swizzled
              __half* __restrict__ hA_next,
              const float* __restrict__ h_prev,  // fp32 [1024][512]
              const float* __restrict__ m_t,
              const __half* __restrict__ X_t,    // [1024][64] swizzled (this t)
              const __half* __restrict__ Whh2,
              const __half* __restrict__ Wih,
              const float* __restrict__ b_ih,
              const float* __restrict__ b_hh,
              float* __restrict__ h_out,
              float* __restrict__ h_out2) {
    extern __shared__ char smem[];
    const uint32_t sbase = smem_u32(smem);
    const int tid = threadIdx.x;
    const int strip = blockIdx.x;      // 0..15
    const int rb = blockIdx.y * 64;    // 0..960

    const uint32_t mbX = sbase + MB_OFF;
    const uint32_t mbF = mbX + 8;      // mbF+0, mbF+8

    const int w = tid >> 5, lane = tid & 31, g = lane >> 2, t = lane & 3;
    const int wr = w & 1, wc = w >> 1;        // 2 rowgroups(32) x 4 colgroups(24)
    const int r00 = wr * 32 + g;
    const int r10 = r00 + 16;
    const int crb = wc * 24 + g;
    const int g3m = g & 3;
    const int t2 = 2 * t;
    const int hc = wc * 8 + t2;

    if (tid == 0) {
        MBARRIER_INIT(mbX, 1);
        MBARRIER_INIT(mbF, 1);
        MBARRIER_INIT(mbF + 8, 1);
    }
    __syncthreads();

    const __half* Bsrc = Whh2 + (size_t)strip * 8 * 96 * 64;
    if (tid == 0) {
        // x-stage: x tile + W_ih strip
        MBARRIER_EXPECT_TX(mbX, 20480);
        BULK_G2S(sbase + XW_OFF, X_t + (size_t)rb * 64, 8192, mbX);
        BULK_G2S(sbase + XW_OFF + 8192, Wih + (size_t)strip * 96 * 64, 12288, mbX);
        // h stages 0,1 (kst 0..3)
        #pragma unroll
        for (int s = 0; s < 2; s++) {
            const uint32_t hb = sbase + HSTG + s * 40960;
            MBARRIER_EXPECT_TX(mbF + 8 * s, 40960);
            BULK_G2S(hb,         hA + ((size_t)(2 * s) * NN + rb) * 64, 8192, mbF + 8 * s);
            BULK_G2S(hb + 8192,  hA + ((size_t)(2 * s + 1) * NN + rb) * 64, 8192,
                     mbF + 8 * s);
            BULK_G2S(hb + 16384, Bsrc + (size_t)(2 * s) * 96 * 64, 12288, mbF + 8 * s);
            BULK_G2S(hb + 28672, Bsrc + (size_t)(2 * s + 1) * 96 * 64, 12288,
                     mbF + 8 * s);
        }
    }

    // ---- epilogue operand preloads ----
    float mreg[2][2];
    float2 hpr[2][2];
    #pragma unroll
    for (int f = 0; f < 2; f++)
        #pragma unroll
        for (int rs = 0; rs < 2; rs++) {
            const int R = rb + wr * 32 + f * 16 + g + 8 * rs;
            mreg[f][rs] = m_t[R];
            hpr[f][rs] = *reinterpret_cast<const float2*>(
                &h_prev[(size_t)R * HH + strip * 32 + hc]);
        }
    const int gcol = strip * 32 + hc;
    const float2 bir = *reinterpret_cast<const float2*>(&b_ih[gcol]);
    const float2 biz = *reinterpret_cast<const float2*>(&b_ih[512 + gcol]);
    const float2 bin = *reinterpret_cast<const float2*>(&b_ih[1024 + gcol]);
    const float2 bhr = *reinterpret_cast<const float2*>(&b_hh[gcol]);
    const float2 bhz = *reinterpret_cast<const float2*>(&b_hh[512 + gcol]);
    const float2 bhn = *reinterpret_cast<const float2*>(&b_hh[1024 + gcol]);

    float acc[2][3][4];     // r, z, h_n (h contributions; r/z also take x)
    float accxn[2][4];      // x contribution to n gate (kept separate)
    #pragma unroll
    for (int f = 0; f < 2; f++) {
        #pragma unroll
        for (int j = 0; j < 3; j++)
            #pragma unroll
            for (int q = 0; q < 4; q++) acc[f][j][q] = 0.0f;
        #pragma unroll
        for (int q = 0; q < 4; q++) accxn[f][q] = 0.0f;
    }

    // ---- x stage (K=64): r,z -> shared accs; n -> accxn ----
    {
        MBARRIER_WAIT_PARITY(mbX, 0);
        const __half* As = (const __half*)(smem + XW_OFF);
        const __half* Bs = (const __half*)(smem + XW_OFF + 8192);
        #pragma unroll
        for (int c = 0; c < 4; c++) {
            const int koff = ((c ^ g3m) * 16) + 4 * t;
            uint2 a00 = *reinterpret_cast<const uint2*>(&As[r00 * 64 + koff]);
            uint2 a01 = *reinterpret_cast<const uint2*>(&As[(r00 + 8) * 64 + koff]);
            uint2 a10 = *reinterpret_cast<const uint2*>(&As[r10 * 64 + koff]);
            uint2 a11 = *reinterpret_cast<const uint2*>(&As[(r10 + 8) * 64 + koff]);
            uint2 b0 = *reinterpret_cast<const uint2*>(&Bs[crb * 64 + koff]);
            uint2 b1 = *reinterpret_cast<const uint2*>(&Bs[(crb + 8) * 64 + koff]);
            uint2 b2 = *reinterpret_cast<const uint2*>(&Bs[(crb + 16) * 64 + koff]);
            mma_f16(acc[0][0], a00.x, a01.x, a00.y, a01.y, b0.x, b0.y);
            mma_f16(acc[0][1], a00.x, a01.x, a00.y, a01.y, b1.x, b1.y);
            mma_f16(accxn[0],  a00.x, a01.x, a00.y, a01.y, b2.x, b2.y);
            mma_f16(acc[1][0], a10.x, a11.x, a10.y, a11.y, b0.x, b0.y);
            mma_f16(acc[1][1], a10.x, a11.x, a10.y, a11.y, b1.x, b1.y);
            mma_f16(accxn[1],  a10.x, a11.x, a10.y, a11.y, b2.x, b2.y);
        }
    }

    // ---- 4 h stages (K=128 each), NBUF=2; syncs only after stages 0,1 ----
    #pragma unroll
    for (int s = 0; s < 4; s++) {
        const int buf = s & 1;
        MBARRIER_WAIT_PARITY(mbF + 8 * buf, (s >> 1) & 1);
        const __half* As = (const __half*)(smem + HSTG + buf * 40960);
        const __half* Bs = (const __half*)(smem + HSTG + buf * 40960 + 16384);
        #pragma unroll
        for (int k8 = 0; k8 < 8; k8++) {
            const __half* Asub = As + ((k8 >= 4) ? 4096 : 0);
            const __half* Bsub = Bs + ((k8 >= 4) ? 6144 : 0);
            const int koff = (((k8 & 3) ^ g3m) * 16) + 4 * t;
            uint2 a00 = *reinterpret_cast<const uint2*>(&Asub[r00 * 64 + koff]);
            uint2 a01 = *reinterpret_cast<const uint2*>(&Asub[(r00 + 8) * 64 + koff]);
            uint2 a10 = *reinterpret_cast<const uint2*>(&Asub[r10 * 64 + koff]);
            uint2 a11 = *reinterpret_cast<const uint2*>(&Asub[(r10 + 8) * 64 + koff]);
            uint2 b0 = *reinterpret_cast<const uint2*>(&Bsub[crb * 64 + koff]);
            uint2 b1 = *reinterpret_cast<const uint2*>(&Bsub[(crb + 8) * 64 + koff]);
            uint2 b2 = *reinterpret_cast<const uint2*>(&Bsub[(crb + 16) * 64 + koff]);
            mma_f16(acc[0][0], a00.x, a01.x, a00.y, a01.y, b0.x, b0.y);
            mma_f16(acc[0][1], a00.x, a01.x, a00.y, a01.y, b1.x, b1.y);
            mma_f16(acc[0][2], a00.x, a01.x, a00.y, a01.y, b2.x, b2.y);
            mma_f16(acc[1][0], a10.x, a11.x, a10.y, a11.y, b0.x, b0.y);
            mma_f16(acc[1][1], a10.x, a11.x, a10.y, a11.y, b1.x, b1.y);
            mma_f16(acc[1][2], a10.x, a11.x, a10.y, a11.y, b2.x, b2.y);
        }
        if (s < 2) {
            __syncthreads();
            if (tid == 0) {
                const int s2 = s + 2;
                const uint32_t hb = sbase + HSTG + buf * 40960;
                MBARRIER_EXPECT_TX(mbF + 8 * buf, 40960);
                BULK_G2S(hb,         hA + ((size_t)(2 * s2) * NN + rb) * 64, 8192,
                         mbF + 8 * buf);
                BULK_G2S(hb + 8192,  hA + ((size_t)(2 * s2 + 1) * NN + rb) * 64, 8192,
                         mbF + 8 * buf);
                BULK_G2S(hb + 16384, Bsrc + (size_t)(2 * s2) * 96 * 64, 12288,
                         mbF + 8 * buf);
                BULK_G2S(hb + 28672, Bsrc + (size_t)(2 * s2 + 1) * 96 * 64, 12288,
                         mbF + 8 * buf);
            }
        }
    }

    // ---- fragment-direct epilogue ----
    const int kstO = strip >> 1;
    const int khO = (strip & 1) * 32 + hc;

    #pragma unroll
    for (int f = 0; f < 2; f++) {
        #pragma unroll
        for (int rs = 0; rs < 2; rs++) {
            const int Rl = wr * 32 + f * 16 + g + 8 * rs;
            const int R = rb + Rl;
            const float m = mreg[f][rs];
            const float sr0 = acc[f][0][2 * rs], sr1 = acc[f][0][2 * rs + 1];
            const float sz0 = acc[f][1][2 * rs], sz1 = acc[f][1][2 * rs + 1];
            const float sn0 = acc[f][2][2 * rs], sn1 = acc[f][2][2 * rs + 1];
            const float xn0 = accxn[f][2 * rs],  xn1 = accxn[f][2 * rs + 1];
            const float2 hp = hpr[f][rs];

            float rv0 = sigf(fmaf(m, sr0, bir.x + bhr.x));
            float rv1 = sigf(fmaf(m, sr1, bir.y + bhr.y));
            float zv0 = sigf(fmaf(m, sz0, biz.x + bhz.x));
            float zv1 = sigf(fmaf(m, sz1, biz.y + bhz.y));
            float nv0 = tanhf(fmaf(m, xn0, bin.x) + rv0 * fmaf(m, sn0, bhn.x));
            float nv1 = tanhf(fmaf(m, xn1, bin.y) + rv1 * fmaf(m, sn1, bhn.y));
            float h0 = fmaf(zv0, fmaf(m, hp.x, -nv0), nv0);
            float h1 = fmaf(zv1, fmaf(m, hp.y, -nv1), nv1);

            *reinterpret_cast<float2*>(&h_out[(size_t)R * HH + gcol]) =
                make_float2(h0, h1);
            if (h_out2)
                *reinterpret_cast<float2*>(&h_out2[(size_t)R * HH + gcol]) =
                    make_float2(h0, h1);
            __half2 oc = __floats2half2_rn(h0, h1);
            *reinterpret_cast<__half2*>(
                &hA_next[((size_t)kstO * NN + R) * 64 + (khO ^ (16 * (R & 3)))]) = oc;
        }
    }
}

// ---------------- host ----------------
extern "C" void kernel_launch(void* const* d_in, const int* in_sizes, int n_in,
                              void* d_out, int out_size) {
    const float* hxs   = (const float*)d_in[0];
    const float* masks = (const float*)d_in[2];
    const float* pact  = (const float*)d_in[3];
    const float* W_ih  = (const float*)d_in[4];
    const float* W_hh  = (const float*)d_in[5];
    const float* b_ih  = (const float*)d_in[6];
    const float* b_hh  = (const float*)d_in[7];
    float* out = (float*)d_out;

    static bool attr_set = false;
    if (!attr_set) {
        cudaFuncSetAttribute(gru_step, cudaFuncAttributeMaxDynamicSharedMemorySize,
                             SMEM_STEP);
        attr_set = true;
    }

    static __half* hA0 = nullptr;
    static __half* gX = nullptr;
    static __half* gW2 = nullptr;
    static __half* gWi = nullptr;
    if (!hA0) cudaGetSymbolAddress((void**)&hA0, g_hA2h);
    if (!gX)  cudaGetSymbolAddress((void**)&gX, g_Xh);
    if (!gW2) cudaGetSymbolAddress((void**)&gW2, g_Whh2h);
    if (!gWi) cudaGetSymbolAddress((void**)&gWi, g_Wih_h);

    // 1) prep (covers X conversion: T*N*I = 8.4M threads)
    {
        int total = TT * NN * II;
        prep_kernel<<<(total + 255) / 256, 256>>>(W_hh, W_ih, hxs, pact);
    }

    // 2) sequential steps
    const size_t stepElems = (size_t)NN * HH;
    const size_t hASz = (size_t)8 * NN * 64;
    const bool has_tail = (size_t)out_size >= (size_t)TT * stepElems + stepElems;

    dim3 grid(NSTRIP, NN / 64);                  // (16, 16) = 256 CTAs, 2/SM
    for (int tstep = 0; tstep < TT; tstep++) {
        const float* h_prev = (tstep == 0) ? hxs : out + (size_t)(tstep - 1) * stepElems;
        float* h_out  = out + (size_t)tstep * stepElems;
        float* h_out2 = (tstep == TT - 1 && has_tail) ? out + (size_t)TT * stepElems
                                                      : nullptr;
        const __half* hA_cur  = hA0 + (size_t)(tstep & 1) * hASz;
        __half*       hA_next = hA0 + (size_t)((tstep + 1) & 1) * hASz;
        gru_step<<<grid, NTH, SMEM_STEP>>>(
            hA_cur, hA_next, h_prev,
            masks + (size_t)tstep * NN,
            gX + (size_t)tstep * NN * II,
            gW2, gWi, b_ih, b_hh, h_out, h_out2);
    }
}

// round 15
// speedup vs baseline: 2.7891x; 1.1526x over previous
#include <cuda_runtime.h>
#include <cuda_fp16.h>
#include <math.h>
#include <stdint.h>

// ---------------- problem dims ----------------
#define TT 128
#define NN 1024
#define HH 512
#define II 64
#define G3 1536
#define NSTRIP 16
#define NTH 256

// ---------------- device scratch ----------------
__device__ __half g_Whh2h[NSTRIP * 8 * 96 * 64];   // [strip][kst64][96 cr][64 k] swz
__device__ __half g_Wih_h[NSTRIP * 96 * 64];       // [strip][96 cr][64 k] swz
__device__ __half g_Xh[(size_t)TT * NN * II];      // [t][n][64] swz by 16*(n&3)
__device__ __half g_hA2h[2][8 * NN * 64];          // fp16 h ping-pong

// ---------------- helpers ----------------
__device__ __forceinline__ uint32_t smem_u32(const void* p) {
    uint32_t a;
    asm("{ .reg .u64 t; cvta.to.shared.u64 t, %1; cvt.u32.u64 %0, t; }" : "=r"(a) : "l"(p));
    return a;
}
__device__ __forceinline__ float sigf(float x) { return 1.0f / (1.0f + __expf(-x)); }

#define MBARRIER_INIT(addr, cnt) \
    asm volatile("mbarrier.init.shared.b64 [%0], %1;" :: "r"(addr), "r"(cnt) : "memory")
#define MBARRIER_EXPECT_TX(addr, tx) \
    asm volatile("mbarrier.arrive.expect_tx.shared.b64 _, [%0], %1;" \
                 :: "r"(addr), "r"(tx) : "memory")
#define MBARRIER_WAIT_PARITY(mbar_addr, phase_parity) do {                                 \
    uint32_t _mbar = (uint32_t)(mbar_addr);                                                \
    uint32_t _parity = (uint32_t)(phase_parity);                                           \
    uint32_t _done;                                                                        \
    asm volatile(                                                                          \
        "{\n\t.reg .pred p;\n\t"                                                           \
        "mbarrier.try_wait.parity.acquire.cta.shared::cta.b64 p, [%1], %2;\n\t"            \
        "selp.b32 %0, 1, 0, p;\n\t}"                                                       \
        : "=r"(_done) : "r"(_mbar), "r"(_parity) : "memory");                              \
    if (!_done) {                                                                          \
        asm volatile(                                                                      \
            "{\n\t.reg .pred P1;\n\t"                                                      \
            "WAIT_LOOP_%=:\n\t"                                                            \
            "mbarrier.try_wait.parity.acquire.cta.shared::cta.b64 P1, [%0], %1, 0x989680;\n\t" \
            "@P1 bra.uni WAIT_DONE_%=;\n\t"                                                \
            "bra.uni WAIT_LOOP_%=;\n\t"                                                    \
            "WAIT_DONE_%=:\n\t}"                                                           \
            :: "r"(_mbar), "r"(_parity) : "memory");                                       \
    }                                                                                      \
} while (0)

#define BULK_G2S(dst_smem, src_gmem, bytes, mbar) \
    asm volatile("cp.async.bulk.shared::cluster.global.mbarrier::complete_tx::bytes " \
                 "[%0], [%1], %2, [%3];" \
                 :: "r"(dst_smem), "l"(src_gmem), "r"(bytes), "r"(mbar) : "memory")

__device__ __forceinline__ void mma_f16(float (&c)[4], uint32_t a0, uint32_t a1,
                                        uint32_t a2, uint32_t a3,
                                        uint32_t b0, uint32_t b1) {
    asm volatile(
        "mma.sync.aligned.m16n8k16.row.col.f32.f16.f16.f32 "
        "{%0,%1,%2,%3}, {%4,%5,%6,%7}, {%8,%9}, {%0,%1,%2,%3};"
        : "+f"(c[0]), "+f"(c[1]), "+f"(c[2]), "+f"(c[3])
        : "r"(a0), "r"(a1), "r"(a2), "r"(a3), "r"(b0), "r"(b1));
}

// ================= prep: all fp16 layouts =================
__global__ void prep_kernel(const float* __restrict__ W_hh,
                            const float* __restrict__ W_ih,
                            const float* __restrict__ hxs,
                            const float* __restrict__ X) {
    int idx = blockIdx.x * blockDim.x + threadIdx.x;
    if (idx < G3 * HH) {
        int r = idx >> 9, k = idx & 511;
        int gg = r >> 9, u = r & 511, s = u >> 5, c = u & 31;
        int cr = (c >> 3) * 24 + gg * 8 + (c & 7);
        int kst = k >> 6, kk = k & 63;
        g_Whh2h[((s * 8 + kst) * 96 + cr) * 64 + (kk ^ (16 * (cr & 3)))] =
            __float2half_rn(W_hh[idx]);
    }
    if (idx < G3 * II) {
        int r = idx >> 6, k = idx & 63;
        int gg = r >> 9, u = r & 511, s = u >> 5, c = u & 31;
        int cr = (c >> 3) * 24 + gg * 8 + (c & 7);
        g_Wih_h[(s * 96 + cr) * 64 + (k ^ (16 * (cr & 3)))] = __float2half_rn(W_ih[idx]);
    }
    if (idx < NN * HH) {
        int n = idx >> 9, k = idx & 511;
        int kst = k >> 6, kk = k & 63;
        g_hA2h[0][(kst * NN + n) * 64 + (kk ^ (16 * (n & 3)))] =
            __float2half_rn(hxs[idx]);
    }
    if (idx < TT * NN * II) {
        int tn = idx >> 6, k = idx & 63;
        int n = tn & 1023;
        g_Xh[(size_t)tn * 64 + (k ^ (16 * (n & 3)))] = __float2half_rn(X[idx]);
    }
}

// ================= per-step kernel: PDL + fused x-stage + 4 K128 h-stages ======
#define XW_OFF 0                        // x 8 KB @0, Wih 12 KB @8192
#define HSTG 20480                      // 2 x 40960 h-stage buffers
#define MB_OFF (HSTG + 2 * 40960)       // mbX @0, mbF0 @8, mbF1 @16
#define SMEM_STEP (MB_OFF + 64)         // 102464 -> 2 CTAs/SM

__global__ __launch_bounds__(NTH, 2)
void gru_step(const __half* __restrict__ hA,     // [kst64][1024][64] swizzled
              __half* __restrict__ hA_next,
              const float* __restrict__ h_prev,  // fp32 [1024][512]
              const float* __restrict__ m_t,
              const __half* __restrict__ X_t,    // [1024][64] swizzled (this t)
              const __half* __restrict__ Whh2,
              const __half* __restrict__ Wih,
              const float* __restrict__ b_ih,
              const float* __restrict__ b_hh,
              float* __restrict__ h_out,
              float* __restrict__ h_out2) {
    extern __shared__ char smem[];
    const uint32_t sbase = smem_u32(smem);
    const int tid = threadIdx.x;
    const int strip = blockIdx.x;      // 0..15
    const int rb = blockIdx.y * 64;    // 0..960

    const uint32_t mbX = sbase + MB_OFF;
    const uint32_t mbF = mbX + 8;

    const int w = tid >> 5, lane = tid & 31, g = lane >> 2, t = lane & 3;
    const int wr = w & 1, wc = w >> 1;
    const int r00 = wr * 32 + g;
    const int r10 = r00 + 16;
    const int crb = wc * 24 + g;
    const int g3m = g & 3;
    const int t2 = 2 * t;
    const int hc = wc * 8 + t2;

    if (tid == 0) {
        MBARRIER_INIT(mbX, 1);
        MBARRIER_INIT(mbF, 1);
        MBARRIER_INIT(mbF + 8, 1);
    }
    __syncthreads();

    // ===== PRE-SYNC: step-independent prefetches (weights, X, biases) =====
    const __half* Bsrc = Whh2 + (size_t)strip * 8 * 96 * 64;
    if (tid == 0) {
        MBARRIER_EXPECT_TX(mbX, 20480);
        BULK_G2S(sbase + XW_OFF, X_t + (size_t)rb * 64, 8192, mbX);
        BULK_G2S(sbase + XW_OFF + 8192, Wih + (size_t)strip * 96 * 64, 12288, mbX);
        #pragma unroll
        for (int s = 0; s < 2; s++) {
            const uint32_t hb = sbase + HSTG + s * 40960;
            MBARRIER_EXPECT_TX(mbF + 8 * s, 40960);          // covers B now + A later
            BULK_G2S(hb + 16384, Bsrc + (size_t)(2 * s) * 96 * 64, 12288, mbF + 8 * s);
            BULK_G2S(hb + 28672, Bsrc + (size_t)(2 * s + 1) * 96 * 64, 12288,
                     mbF + 8 * s);
        }
    }
    const int gcol = strip * 32 + hc;
    const float2 bir = *reinterpret_cast<const float2*>(&b_ih[gcol]);
    const float2 biz = *reinterpret_cast<const float2*>(&b_ih[512 + gcol]);
    const float2 bin = *reinterpret_cast<const float2*>(&b_ih[1024 + gcol]);
    const float2 bhr = *reinterpret_cast<const float2*>(&b_hh[gcol]);
    const float2 bhz = *reinterpret_cast<const float2*>(&b_hh[512 + gcol]);
    const float2 bhn = *reinterpret_cast<const float2*>(&b_hh[1024 + gcol]);

    // ===== wait for the previous step's kernel to fully complete =====
    cudaGridDependencySynchronize();
    // allow the NEXT step's kernel to begin its pre-sync prefetches
    cudaTriggerProgrammaticLaunchCompletion();

    // ===== POST-SYNC: dependent loads (hA bulks, h_prev, masks) =====
    if (tid == 0) {
        #pragma unroll
        for (int s = 0; s < 2; s++) {
            const uint32_t hb = sbase + HSTG + s * 40960;
            BULK_G2S(hb,        hA + ((size_t)(2 * s) * NN + rb) * 64, 8192, mbF + 8 * s);
            BULK_G2S(hb + 8192, hA + ((size_t)(2 * s + 1) * NN + rb) * 64, 8192,
                     mbF + 8 * s);
        }
    }
    float mreg[2][2];
    float2 hpr[2][2];
    #pragma unroll
    for (int f = 0; f < 2; f++)
        #pragma unroll
        for (int rs = 0; rs < 2; rs++) {
            const int R = rb + wr * 32 + f * 16 + g + 8 * rs;
            mreg[f][rs] = m_t[R];
            hpr[f][rs] = *reinterpret_cast<const float2*>(
                &h_prev[(size_t)R * HH + strip * 32 + hc]);
        }

    float acc[2][3][4];
    float accxn[2][4];
    #pragma unroll
    for (int f = 0; f < 2; f++) {
        #pragma unroll
        for (int j = 0; j < 3; j++)
            #pragma unroll
            for (int q = 0; q < 4; q++) acc[f][j][q] = 0.0f;
        #pragma unroll
        for (int q = 0; q < 4; q++) accxn[f][q] = 0.0f;
    }

    // ---- x stage (K=64) ----
    {
        MBARRIER_WAIT_PARITY(mbX, 0);
        const __half* As = (const __half*)(smem + XW_OFF);
        const __half* Bs = (const __half*)(smem + XW_OFF + 8192);
        #pragma unroll
        for (int c = 0; c < 4; c++) {
            const int koff = ((c ^ g3m) * 16) + 4 * t;
            uint2 a00 = *reinterpret_cast<const uint2*>(&As[r00 * 64 + koff]);
            uint2 a01 = *reinterpret_cast<const uint2*>(&As[(r00 + 8) * 64 + koff]);
            uint2 a10 = *reinterpret_cast<const uint2*>(&As[r10 * 64 + koff]);
            uint2 a11 = *reinterpret_cast<const uint2*>(&As[(r10 + 8) * 64 + koff]);
            uint2 b0 = *reinterpret_cast<const uint2*>(&Bs[crb * 64 + koff]);
            uint2 b1 = *reinterpret_cast<const uint2*>(&Bs[(crb + 8) * 64 + koff]);
            uint2 b2 = *reinterpret_cast<const uint2*>(&Bs[(crb + 16) * 64 + koff]);
            mma_f16(acc[0][0], a00.x, a01.x, a00.y, a01.y, b0.x, b0.y);
            mma_f16(acc[0][1], a00.x, a01.x, a00.y, a01.y, b1.x, b1.y);
            mma_f16(accxn[0],  a00.x, a01.x, a00.y, a01.y, b2.x, b2.y);
            mma_f16(acc[1][0], a10.x, a11.x, a10.y, a11.y, b0.x, b0.y);
            mma_f16(acc[1][1], a10.x, a11.x, a10.y, a11.y, b1.x, b1.y);
            mma_f16(accxn[1],  a10.x, a11.x, a10.y, a11.y, b2.x, b2.y);
        }
    }

    // ---- 4 h stages (K=128 each), NBUF=2 ----
    #pragma unroll
    for (int s = 0; s < 4; s++) {
        const int buf = s & 1;
        MBARRIER_WAIT_PARITY(mbF + 8 * buf, (s >> 1) & 1);
        const __half* As = (const __half*)(smem + HSTG + buf * 40960);
        const __half* Bs = (const __half*)(smem + HSTG + buf * 40960 + 16384);
        #pragma unroll
        for (int k8 = 0; k8 < 8; k8++) {
            const __half* Asub = As + ((k8 >= 4) ? 4096 : 0);
            const __half* Bsub = Bs + ((k8 >= 4) ? 6144 : 0);
            const int koff = (((k8 & 3) ^ g3m) * 16) + 4 * t;
            uint2 a00 = *reinterpret_cast<const uint2*>(&Asub[r00 * 64 + koff]);
            uint2 a01 = *reinterpret_cast<const uint2*>(&Asub[(r00 + 8) * 64 + koff]);
            uint2 a10 = *reinterpret_cast<const uint2*>(&Asub[r10 * 64 + koff]);
            uint2 a11 = *reinterpret_cast<const uint2*>(&Asub[(r10 + 8) * 64 + koff]);
            uint2 b0 = *reinterpret_cast<const uint2*>(&Bsub[crb * 64 + koff]);
            uint2 b1 = *reinterpret_cast<const uint2*>(&Bsub[(crb + 8) * 64 + koff]);
            uint2 b2 = *reinterpret_cast<const uint2*>(&Bsub[(crb + 16) * 64 + koff]);
            mma_f16(acc[0][0], a00.x, a01.x, a00.y, a01.y, b0.x, b0.y);
            mma_f16(acc[0][1], a00.x, a01.x, a00.y, a01.y, b1.x, b1.y);
            mma_f16(acc[0][2], a00.x, a01.x, a00.y, a01.y, b2.x, b2.y);
            mma_f16(acc[1][0], a10.x, a11.x, a10.y, a11.y, b0.x, b0.y);
            mma_f16(acc[1][1], a10.x, a11.x, a10.y, a11.y, b1.x, b1.y);
            mma_f16(acc[1][2], a10.x, a11.x, a10.y, a11.y, b2.x, b2.y);
        }
        if (s < 2) {
            __syncthreads();
            if (tid == 0) {
                const int s2 = s + 2;
                const uint32_t hb = sbase + HSTG + buf * 40960;
                MBARRIER_EXPECT_TX(mbF + 8 * buf, 40960);
                BULK_G2S(hb,         hA + ((size_t)(2 * s2) * NN + rb) * 64, 8192,
                         mbF + 8 * buf);
                BULK_G2S(hb + 8192,  hA + ((size_t)(2 * s2 + 1) * NN + rb) * 64, 8192,
                         mbF + 8 * buf);
                BULK_G2S(hb + 16384, Bsrc + (size_t)(2 * s2) * 96 * 64, 12288,
                         mbF + 8 * buf);
                BULK_G2S(hb + 28672, Bsrc + (size_t)(2 * s2 + 1) * 96 * 64, 12288,
                         mbF + 8 * buf);
            }
        }
    }

    // ---- fragment-direct epilogue ----
    const int kstO = strip >> 1;
    const int khO = (strip & 1) * 32 + hc;

    #pragma unroll
    for (int f = 0; f < 2; f++) {
        #pragma unroll
        for (int rs = 0; rs < 2; rs++) {
            const int Rl = wr * 32 + f * 16 + g + 8 * rs;
            const int R = rb + Rl;
            const float m = mreg[f][rs];
            const float sr0 = acc[f][0][2 * rs], sr1 = acc[f][0][2 * rs + 1];
            const float sz0 = acc[f][1][2 * rs], sz1 = acc[f][1][2 * rs + 1];
            const float sn0 = acc[f][2][2 * rs], sn1 = acc[f][2][2 * rs + 1];
            const float xn0 = accxn[f][2 * rs],  xn1 = accxn[f][2 * rs + 1];
            const float2 hp = hpr[f][rs];

            float rv0 = sigf(fmaf(m, sr0, bir.x + bhr.x));
            float rv1 = sigf(fmaf(m, sr1, bir.y + bhr.y));
            float zv0 = sigf(fmaf(m, sz0, biz.x + bhz.x));
            float zv1 = sigf(fmaf(m, sz1, biz.y + bhz.y));
            float nv0 = tanhf(fmaf(m, xn0, bin.x) + rv0 * fmaf(m, sn0, bhn.x));
            float nv1 = tanhf(fmaf(m, xn1, bin.y) + rv1 * fmaf(m, sn1, bhn.y));
            float h0 = fmaf(zv0, fmaf(m, hp.x, -nv0), nv0);
            float h1 = fmaf(zv1, fmaf(m, hp.y, -nv1), nv1);

            *reinterpret_cast<float2*>(&h_out[(size_t)R * HH + gcol]) =
                make_float2(h0, h1);
            if (h_out2)
                *reinterpret_cast<float2*>(&h_out2[(size_t)R * HH + gcol]) =
                    make_float2(h0, h1);
            __half2 oc = __floats2half2_rn(h0, h1);
            *reinterpret_cast<__half2*>(
                &hA_next[((size_t)kstO * NN + R) * 64 + (khO ^ (16 * (R & 3)))]) = oc;
        }
    }
}

// ---------------- host ----------------
extern "C" void kernel_launch(void* const* d_in, const int* in_sizes, int n_in,
                              void* d_out, int out_size) {
    const float* hxs   = (const float*)d_in[0];
    const float* masks = (const float*)d_in[2];
    const float* pact  = (const float*)d_in[3];
    const float* W_ih  = (const float*)d_in[4];
    const float* W_hh  = (const float*)d_in[5];
    const float* b_ih  = (const float*)d_in[6];
    const float* b_hh  = (const float*)d_in[7];
    float* out = (float*)d_out;

    static bool attr_set = false;
    if (!attr_set) {
        cudaFuncSetAttribute(gru_step, cudaFuncAttributeMaxDynamicSharedMemorySize,
                             SMEM_STEP);
        attr_set = true;
    }

    static __half* hA0 = nullptr;
    static __half* gX = nullptr;
    static __half* gW2 = nullptr;
    static __half* gWi = nullptr;
    if (!hA0) cudaGetSymbolAddress((void**)&hA0, g_hA2h);
    if (!gX)  cudaGetSymbolAddress((void**)&gX, g_Xh);
    if (!gW2) cudaGetSymbolAddress((void**)&gW2, g_Whh2h);
    if (!gWi) cudaGetSymbolAddress((void**)&gWi, g_Wih_h);

    // 1) prep
    {
        int total = TT * NN * II;
        prep_kernel<<<(total + 255) / 256, 256>>>(W_hh, W_ih, hxs, pact);
    }

    // 2) sequential steps with PDL chaining
    const size_t stepElems = (size_t)NN * HH;
    const size_t hASz = (size_t)8 * NN * 64;
    const bool has_tail = (size_t)out_size >= (size_t)TT * stepElems + stepElems;

    dim3 grid(NSTRIP, NN / 64);                  // (16, 16) = 256 CTAs, 2/SM
    for (int tstep = 0; tstep < TT; tstep++) {
        const float* h_prev = (tstep == 0) ? hxs : out + (size_t)(tstep - 1) * stepElems;
        float* h_out  = out + (size_t)tstep * stepElems;
        float* h_out2 = (tstep == TT - 1 && has_tail) ? out + (size_t)TT * stepElems
                                                      : nullptr;
        const __half* hA_cur  = hA0 + (size_t)(tstep & 1) * hASz;
        __half*       hA_next = hA0 + (size_t)((tstep + 1) & 1) * hASz;
        const __half* X_t = gX + (size_t)tstep * NN * II;
        const float* m_p = masks + (size_t)tstep * NN;

        cudaLaunchConfig_t cfg = {};
        cfg.gridDim = grid;
        cfg.blockDim = dim3(NTH, 1, 1);
        cfg.dynamicSmemBytes = SMEM_STEP;
        cfg.stream = 0;
        cudaLaunchAttribute attrs[1];
        attrs[0].id = cudaLaunchAttributeProgrammaticStreamSerialization;
        attrs[0].val.programmaticStreamSerializationAllowed = 1;
        // step 0 must NOT overlap with prep (its pre-sync reads are prep outputs)
        cfg.attrs = attrs;
        cfg.numAttrs = (tstep == 0) ? 0 : 1;

        cudaLaunchKernelEx(&cfg, gru_step,
                           hA_cur, hA_next, h_prev, m_p, X_t,
                           (const __half*)gW2, (const __half*)gWi,
                           b_ih, b_hh, h_out, h_out2);
    }
}

// round 16
// speedup vs baseline: 2.8810x; 1.0330x over previous
#include <cuda_runtime.h>
#include <cuda_fp16.h>
#include <math.h>
#include <stdint.h>

// ---------------- problem dims ----------------
#define TT 128
#define NN 1024
#define HH 512
#define II 64
#define G3 1536
#define NSTRIP 16
#define NTH 256

// ---------------- device scratch ----------------
__device__ __half g_Whh2h[NSTRIP * 8 * 96 * 64];   // [strip][kst64][96 cr][64 k] swz
__device__ __half g_Wih_h[NSTRIP * 96 * 64];       // [strip][96 cr][64 k] swz
__device__ __half g_Xh[(size_t)TT * NN * II];      // [t][n][64] swz by 16*(n&3)
__device__ __half g_hA2h[2][8 * NN * 64];          // fp16 h ping-pong

// ---------------- helpers ----------------
__device__ __forceinline__ uint32_t smem_u32(const void* p) {
    uint32_t a;
    asm("{ .reg .u64 t; cvta.to.shared.u64 t, %1; cvt.u32.u64 %0, t; }" : "=r"(a) : "l"(p));
    return a;
}
__device__ __forceinline__ float sigf(float x) { return 1.0f / (1.0f + __expf(-x)); }

#define MBARRIER_INIT(addr, cnt) \
    asm volatile("mbarrier.init.shared.b64 [%0], %1;" :: "r"(addr), "r"(cnt) : "memory")
#define MBARRIER_EXPECT_TX(addr, tx) \
    asm volatile("mbarrier.arrive.expect_tx.shared.b64 _, [%0], %1;" \
                 :: "r"(addr), "r"(tx) : "memory")
#define MBARRIER_WAIT_PARITY(mbar_addr, phase_parity) do {                                 \
    uint32_t _mbar = (uint32_t)(mbar_addr);                                                \
    uint32_t _parity = (uint32_t)(phase_parity);                                           \
    uint32_t _done;                                                                        \
    asm volatile(                                                                          \
        "{\n\t.reg .pred p;\n\t"                                                           \
        "mbarrier.try_wait.parity.acquire.cta.shared::cta.b64 p, [%1], %2;\n\t"            \
        "selp.b32 %0, 1, 0, p;\n\t}"                                                       \
        : "=r"(_done) : "r"(_mbar), "r"(_parity) : "memory");                              \
    if (!_done) {                                                                          \
        asm volatile(                                                                      \
            "{\n\t.reg .pred P1;\n\t"                                                      \
            "WAIT_LOOP_%=:\n\t"                                                            \
            "mbarrier.try_wait.parity.acquire.cta.shared::cta.b64 P1, [%0], %1, 0x989680;\n\t" \
            "@P1 bra.uni WAIT_DONE_%=;\n\t"                                                \
            "bra.uni WAIT_LOOP_%=;\n\t"                                                    \
            "WAIT_DONE_%=:\n\t}"                                                           \
            :: "r"(_mbar), "r"(_parity) : "memory");                                       \
    }                                                                                      \
} while (0)

#define BULK_G2S(dst_smem, src_gmem, bytes, mbar) \
    asm volatile("cp.async.bulk.shared::cluster.global.mbarrier::complete_tx::bytes " \
                 "[%0], [%1], %2, [%3];" \
                 :: "r"(dst_smem), "l"(src_gmem), "r"(bytes), "r"(mbar) : "memory")

__device__ __forceinline__ void mma_f16(float (&c)[4], uint32_t a0, uint32_t a1,
                                        uint32_t a2, uint32_t a3,
                                        uint32_t b0, uint32_t b1) {
    asm volatile(
        "mma.sync.aligned.m16n8k16.row.col.f32.f16.f16.f32 "
        "{%0,%1,%2,%3}, {%4,%5,%6,%7}, {%8,%9}, {%0,%1,%2,%3};"
        : "+f"(c[0]), "+f"(c[1]), "+f"(c[2]), "+f"(c[3])
        : "r"(a0), "r"(a1), "r"(a2), "r"(a3), "r"(b0), "r"(b1));
}

// ================= prep: all fp16 layouts =================
__global__ void prep_kernel(const float* __restrict__ W_hh,
                            const float* __restrict__ W_ih,
                            const float* __restrict__ hxs,
                            const float* __restrict__ X) {
    int idx = blockIdx.x * blockDim.x + threadIdx.x;
    if (idx < G3 * HH) {
        int r = idx >> 9, k = idx & 511;
        int gg = r >> 9, u = r & 511, s = u >> 5, c = u & 31;
        int cr = (c >> 3) * 24 + gg * 8 + (c & 7);
        int kst = k >> 6, kk = k & 63;
        g_Whh2h[((s * 8 + kst) * 96 + cr) * 64 + (kk ^ (16 * (cr & 3)))] =
            __float2half_rn(W_hh[idx]);
    }
    if (idx < G3 * II) {
        int r = idx >> 6, k = idx & 63;
        int gg = r >> 9, u = r & 511, s = u >> 5, c = u & 31;
        int cr = (c >> 3) * 24 + gg * 8 + (c & 7);
        g_Wih_h[(s * 96 + cr) * 64 + (k ^ (16 * (cr & 3)))] = __float2half_rn(W_ih[idx]);
    }
    if (idx < NN * HH) {
        int n = idx >> 9, k = idx & 511;
        int kst = k >> 6, kk = k & 63;
        g_hA2h[0][(kst * NN + n) * 64 + (kk ^ (16 * (n & 3)))] =
            __float2half_rn(hxs[idx]);
    }
    if (idx < TT * NN * II) {
        int tn = idx >> 6, k = idx & 63;
        int n = tn & 1023;
        g_Xh[(size_t)tn * 64 + (k ^ (16 * (n & 3)))] = __float2half_rn(X[idx]);
    }
}

// ================= per-step kernel: PDL, x-stage pre-sync ======================
#define XW_OFF 0                        // x 8 KB @0, Wih 12 KB @8192
#define HSTG 20480                      // 2 x 40960 h-stage buffers
#define MB_OFF (HSTG + 2 * 40960)       // mbX @0, mbF0 @8, mbF1 @16
#define SMEM_STEP (MB_OFF + 64)         // 102464 -> 2 CTAs/SM

__global__ __launch_bounds__(NTH, 2)
void gru_step(const __half* __restrict__ hA,     // [kst64][1024][64] swizzled
              __half* __restrict__ hA_next,
              const float* __restrict__ h_prev,  // fp32 [1024][512]
              const float* __restrict__ m_t,
              const __half* __restrict__ X_t,    // [1024][64] swizzled (this t)
              const __half* __restrict__ Whh2,
              const __half* __restrict__ Wih,
              const float* __restrict__ b_ih,
              const float* __restrict__ b_hh,
              float* __restrict__ h_out,
              float* __restrict__ h_out2) {
    extern __shared__ char smem[];
    const uint32_t sbase = smem_u32(smem);
    const int tid = threadIdx.x;
    const int strip = blockIdx.x;      // 0..15
    const int rb = blockIdx.y * 64;    // 0..960

    const uint32_t mbX = sbase + MB_OFF;
    const uint32_t mbF = mbX + 8;

    const int w = tid >> 5, lane = tid & 31, g = lane >> 2, t = lane & 3;
    const int wr = w & 1, wc = w >> 1;
    const int r00 = wr * 32 + g;
    const int r10 = r00 + 16;
    const int crb = wc * 24 + g;
    const int g3m = g & 3;
    const int t2 = 2 * t;
    const int hc = wc * 8 + t2;

    if (tid == 0) {
        MBARRIER_INIT(mbX, 1);
        MBARRIER_INIT(mbF, 1);
        MBARRIER_INIT(mbF + 8, 1);
    }
    __syncthreads();

    // ===== PRE-SYNC: step-independent prefetches + x-GEMM =====
    const __half* Bsrc = Whh2 + (size_t)strip * 8 * 96 * 64;
    if (tid == 0) {
        MBARRIER_EXPECT_TX(mbX, 20480);
        BULK_G2S(sbase + XW_OFF, X_t + (size_t)rb * 64, 8192, mbX);
        BULK_G2S(sbase + XW_OFF + 8192, Wih + (size_t)strip * 96 * 64, 12288, mbX);
        #pragma unroll
        for (int s = 0; s < 2; s++) {
            const uint32_t hb = sbase + HSTG + s * 40960;
            MBARRIER_EXPECT_TX(mbF + 8 * s, 40960);          // covers B now + A later
            BULK_G2S(hb + 16384, Bsrc + (size_t)(2 * s) * 96 * 64, 12288, mbF + 8 * s);
            BULK_G2S(hb + 28672, Bsrc + (size_t)(2 * s + 1) * 96 * 64, 12288,
                     mbF + 8 * s);
        }
    }
    const int gcol = strip * 32 + hc;
    const float2 bir = *reinterpret_cast<const float2*>(&b_ih[gcol]);
    const float2 biz = *reinterpret_cast<const float2*>(&b_ih[512 + gcol]);
    const float2 bin = *reinterpret_cast<const float2*>(&b_ih[1024 + gcol]);
    const float2 bhr = *reinterpret_cast<const float2*>(&b_hh[gcol]);
    const float2 bhz = *reinterpret_cast<const float2*>(&b_hh[512 + gcol]);
    const float2 bhn = *reinterpret_cast<const float2*>(&b_hh[1024 + gcol]);

    // masks are harness inputs -> step-independent, load pre-sync
    float mreg[2][2];
    #pragma unroll
    for (int f = 0; f < 2; f++)
        #pragma unroll
        for (int rs = 0; rs < 2; rs++)
            mreg[f][rs] = m_t[rb + wr * 32 + f * 16 + g + 8 * rs];

    float acc[2][3][4];
    float accxn[2][4];
    #pragma unroll
    for (int f = 0; f < 2; f++) {
        #pragma unroll
        for (int j = 0; j < 3; j++)
            #pragma unroll
            for (int q = 0; q < 4; q++) acc[f][j][q] = 0.0f;
        #pragma unroll
        for (int q = 0; q < 4; q++) accxn[f][q] = 0.0f;
    }

    // ---- x stage (K=64) — fully pre-sync (X/W_ih independent of prior step) ----
    {
        MBARRIER_WAIT_PARITY(mbX, 0);
        const __half* As = (const __half*)(smem + XW_OFF);
        const __half* Bs = (const __half*)(smem + XW_OFF + 8192);
        #pragma unroll
        for (int c = 0; c < 4; c++) {
            const int koff = ((c ^ g3m) * 16) + 4 * t;
            uint2 a00 = *reinterpret_cast<const uint2*>(&As[r00 * 64 + koff]);
            uint2 a01 = *reinterpret_cast<const uint2*>(&As[(r00 + 8) * 64 + koff]);
            uint2 a10 = *reinterpret_cast<const uint2*>(&As[r10 * 64 + koff]);
            uint2 a11 = *reinterpret_cast<const uint2*>(&As[(r10 + 8) * 64 + koff]);
            uint2 b0 = *reinterpret_cast<const uint2*>(&Bs[crb * 64 + koff]);
            uint2 b1 = *reinterpret_cast<const uint2*>(&Bs[(crb + 8) * 64 + koff]);
            uint2 b2 = *reinterpret_cast<const uint2*>(&Bs[(crb + 16) * 64 + koff]);
            mma_f16(acc[0][0], a00.x, a01.x, a00.y, a01.y, b0.x, b0.y);
            mma_f16(acc[0][1], a00.x, a01.x, a00.y, a01.y, b1.x, b1.y);
            mma_f16(accxn[0],  a00.x, a01.x, a00.y, a01.y, b2.x, b2.y);
            mma_f16(acc[1][0], a10.x, a11.x, a10.y, a11.y, b0.x, b0.y);
            mma_f16(acc[1][1], a10.x, a11.x, a10.y, a11.y, b1.x, b1.y);
            mma_f16(accxn[1],  a10.x, a11.x, a10.y, a11.y, b2.x, b2.y);
        }
    }

    // ===== wait for the previous step's kernel to fully complete =====
    cudaGridDependencySynchronize();
    cudaTriggerProgrammaticLaunchCompletion();

    // ===== POST-SYNC: dependent loads (hA bulks first, then h_prev regs) =====
    if (tid == 0) {
        #pragma unroll
        for (int s = 0; s < 2; s++) {
            const uint32_t hb = sbase + HSTG + s * 40960;
            BULK_G2S(hb,        hA + ((size_t)(2 * s) * NN + rb) * 64, 8192, mbF + 8 * s);
            BULK_G2S(hb + 8192, hA + ((size_t)(2 * s + 1) * NN + rb) * 64, 8192,
                     mbF + 8 * s);
        }
    }
    float2 hpr[2][2];
    #pragma unroll
    for (int f = 0; f < 2; f++)
        #pragma unroll
        for (int rs = 0; rs < 2; rs++) {
            const int R = rb + wr * 32 + f * 16 + g + 8 * rs;
            hpr[f][rs] = *reinterpret_cast<const float2*>(
                &h_prev[(size_t)R * HH + strip * 32 + hc]);
        }

    // ---- 4 h stages (K=128 each), NBUF=2 ----
    #pragma unroll
    for (int s = 0; s < 4; s++) {
        const int buf = s & 1;
        MBARRIER_WAIT_PARITY(mbF + 8 * buf, (s >> 1) & 1);
        const __half* As = (const __half*)(smem + HSTG + buf * 40960);
        const __half* Bs = (const __half*)(smem + HSTG + buf * 40960 + 16384);
        #pragma unroll
        for (int k8 = 0; k8 < 8; k8++) {
            const __half* Asub = As + ((k8 >= 4) ? 4096 : 0);
            const __half* Bsub = Bs + ((k8 >= 4) ? 6144 : 0);
            const int koff = (((k8 & 3) ^ g3m) * 16) + 4 * t;
            uint2 a00 = *reinterpret_cast<const uint2*>(&Asub[r00 * 64 + koff]);
            uint2 a01 = *reinterpret_cast<const uint2*>(&Asub[(r00 + 8) * 64 + koff]);
            uint2 a10 = *reinterpret_cast<const uint2*>(&Asub[r10 * 64 + koff]);
            uint2 a11 = *reinterpret_cast<const uint2*>(&Asub[(r10 + 8) * 64 + koff]);
            uint2 b0 = *reinterpret_cast<const uint2*>(&Bsub[crb * 64 + koff]);
            uint2 b1 = *reinterpret_cast<const uint2*>(&Bsub[(crb + 8) * 64 + koff]);
            uint2 b2 = *reinterpret_cast<const uint2*>(&Bsub[(crb + 16) * 64 + koff]);
            mma_f16(acc[0][0], a00.x, a01.x, a00.y, a01.y, b0.x, b0.y);
            mma_f16(acc[0][1], a00.x, a01.x, a00.y, a01.y, b1.x, b1.y);
            mma_f16(acc[0][2], a00.x, a01.x, a00.y, a01.y, b2.x, b2.y);
            mma_f16(acc[1][0], a10.x, a11.x, a10.y, a11.y, b0.x, b0.y);
            mma_f16(acc[1][1], a10.x, a11.x, a10.y, a11.y, b1.x, b1.y);
            mma_f16(acc[1][2], a10.x, a11.x, a10.y, a11.y, b2.x, b2.y);
        }
        if (s < 2) {
            __syncthreads();
            if (tid == 0) {
                const int s2 = s + 2;
                const uint32_t hb = sbase + HSTG + buf * 40960;
                MBARRIER_EXPECT_TX(mbF + 8 * buf, 40960);
                BULK_G2S(hb,         hA + ((size_t)(2 * s2) * NN + rb) * 64, 8192,
                         mbF + 8 * buf);
                BULK_G2S(hb + 8192,  hA + ((size_t)(2 * s2 + 1) * NN + rb) * 64, 8192,
                         mbF + 8 * buf);
                BULK_G2S(hb + 16384, Bsrc + (size_t)(2 * s2) * 96 * 64, 12288,
                         mbF + 8 * buf);
                BULK_G2S(hb + 28672, Bsrc + (size_t)(2 * s2 + 1) * 96 * 64, 12288,
                         mbF + 8 * buf);
            }
        }
    }

    // ---- fragment-direct epilogue ----
    const int kstO = strip >> 1;
    const int khO = (strip & 1) * 32 + hc;

    #pragma unroll
    for (int f = 0; f < 2; f++) {
        #pragma unroll
        for (int rs = 0; rs < 2; rs++) {
            const int Rl = wr * 32 + f * 16 + g + 8 * rs;
            const int R = rb + Rl;
            const float m = mreg[f][rs];
            const float sr0 = acc[f][0][2 * rs], sr1 = acc[f][0][2 * rs + 1];
            const float sz0 = acc[f][1][2 * rs], sz1 = acc[f][1][2 * rs + 1];
            const float sn0 = acc[f][2][2 * rs], sn1 = acc[f][2][2 * rs + 1];
            const float xn0 = accxn[f][2 * rs],  xn1 = accxn[f][2 * rs + 1];
            const float2 hp = hpr[f][rs];

            float rv0 = sigf(fmaf(m, sr0, bir.x + bhr.x));
            float rv1 = sigf(fmaf(m, sr1, bir.y + bhr.y));
            float zv0 = sigf(fmaf(m, sz0, biz.x + bhz.x));
            float zv1 = sigf(fmaf(m, sz1, biz.y + bhz.y));
            float nv0 = tanhf(fmaf(m, xn0, bin.x) + rv0 * fmaf(m, sn0, bhn.x));
            float nv1 = tanhf(fmaf(m, xn1, bin.y) + rv1 * fmaf(m, sn1, bhn.y));
            float h0 = fmaf(zv0, fmaf(m, hp.x, -nv0), nv0);
            float h1 = fmaf(zv1, fmaf(m, hp.y, -nv1), nv1);

            *reinterpret_cast<float2*>(&h_out[(size_t)R * HH + gcol]) =
                make_float2(h0, h1);
            if (h_out2)
                *reinterpret_cast<float2*>(&h_out2[(size_t)R * HH + gcol]) =
                    make_float2(h0, h1);
            __half2 oc = __floats2half2_rn(h0, h1);
            *reinterpret_cast<__half2*>(
                &hA_next[((size_t)kstO * NN + R) * 64 + (khO ^ (16 * (R & 3)))]) = oc;
        }
    }
}

// ---------------- host ----------------
extern "C" void kernel_launch(void* const* d_in, const int* in_sizes, int n_in,
                              void* d_out, int out_size) {
    const float* hxs   = (const float*)d_in[0];
    const float* masks = (const float*)d_in[2];
    const float* pact  = (const float*)d_in[3];
    const float* W_ih  = (const float*)d_in[4];
    const float* W_hh  = (const float*)d_in[5];
    const float* b_ih  = (const float*)d_in[6];
    const float* b_hh  = (const float*)d_in[7];
    float* out = (float*)d_out;

    static bool attr_set = false;
    if (!attr_set) {
        cudaFuncSetAttribute(gru_step, cudaFuncAttributeMaxDynamicSharedMemorySize,
                             SMEM_STEP);
        attr_set = true;
    }

    static __half* hA0 = nullptr;
    static __half* gX = nullptr;
    static __half* gW2 = nullptr;
    static __half* gWi = nullptr;
    if (!hA0) cudaGetSymbolAddress((void**)&hA0, g_hA2h);
    if (!gX)  cudaGetSymbolAddress((void**)&gX, g_Xh);
    if (!gW2) cudaGetSymbolAddress((void**)&gW2, g_Whh2h);
    if (!gWi) cudaGetSymbolAddress((void**)&gWi, g_Wih_h);

    // 1) prep
    {
        int total = TT * NN * II;
        prep_kernel<<<(total + 255) / 256, 256>>>(W_hh, W_ih, hxs, pact);
    }

    // 2) sequential steps with PDL chaining
    const size_t stepElems = (size_t)NN * HH;
    const size_t hASz = (size_t)8 * NN * 64;
    const bool has_tail = (size_t)out_size >= (size_t)TT * stepElems + stepElems;

    dim3 grid(NSTRIP, NN / 64);                  // (16, 16) = 256 CTAs, 2/SM
    for (int tstep = 0; tstep < TT; tstep++) {
        const float* h_prev = (tstep == 0) ? hxs : out + (size_t)(tstep - 1) * stepElems;
        float* h_out  = out + (size_t)tstep * stepElems;
        float* h_out2 = (tstep == TT - 1 && has_tail) ? out + (size_t)TT * stepElems
                                                      : nullptr;
        const __half* hA_cur  = hA0 + (size_t)(tstep & 1) * hASz;
        __half*       hA_next = hA0 + (size_t)((tstep + 1) & 1) * hASz;
        const __half* X_t = gX + (size_t)tstep * NN * II;
        const float* m_p = masks + (size_t)tstep * NN;

        cudaLaunchConfig_t cfg = {};
        cfg.gridDim = grid;
        cfg.blockDim = dim3(NTH, 1, 1);
        cfg.dynamicSmemBytes = SMEM_STEP;
        cfg.stream = 0;
        cudaLaunchAttribute attrs[1];
        attrs[0].id = cudaLaunchAttributeProgrammaticStreamSerialization;
        attrs[0].val.programmaticStreamSerializationAllowed = 1;
        // step 0 must NOT overlap with prep (its pre-sync reads are prep outputs)
        cfg.attrs = attrs;
        cfg.numAttrs = (tstep == 0) ? 0 : 1;

        cudaLaunchKernelEx(&cfg, gru_step,
                           hA_cur, hA_next, h_prev, m_p, X_t,
                           (const __half*)gW2, (const __half*)gWi,
                           b_ih, b_hh, h_out, h_out2);
    }
}

// round 17
// speedup vs baseline: 3.0708x; 1.0659x over previous
#include <cuda_runtime.h>
#include <cuda_fp16.h>
#include <math.h>
#include <stdint.h>

// ---------------- problem dims ----------------
#define TT 128
#define NN 1024
#define HH 512
#define II 64
#define G3 1536
#define NSTRIP 16
#define NTH 256

// ---------------- device scratch ----------------
__device__ __half g_Whh2h[NSTRIP * 8 * 96 * 64];   // [strip][kst64][96 cr][64 k] swz
__device__ __half g_Wih_h[NSTRIP * 96 * 64];       // [strip][96 cr][64 k] swz
__device__ __half g_Xh[(size_t)TT * NN * II];      // [t][n][64] swz by 16*(n&3)
__device__ __half g_hA2h[2][8 * NN * 64];          // fp16 h ping-pong

// ---------------- helpers ----------------
__device__ __forceinline__ uint32_t smem_u32(const void* p) {
    uint32_t a;
    asm("{ .reg .u64 t; cvta.to.shared.u64 t, %1; cvt.u32.u64 %0, t; }" : "=r"(a) : "l"(p));
    return a;
}
// fast activations: MUFU.EX2 + MUFU.RCP only (err ~1e-6, far under budget)
__device__ __forceinline__ float sigf(float x) {
    return __fdividef(1.0f, 1.0f + __expf(-x));
}
__device__ __forceinline__ float tanhf_fast(float x) {
    return __fdividef(2.0f, 1.0f + __expf(-2.0f * x)) - 1.0f;
}

#define MBARRIER_INIT(addr, cnt) \
    asm volatile("mbarrier.init.shared.b64 [%0], %1;" :: "r"(addr), "r"(cnt) : "memory")
#define MBARRIER_EXPECT_TX(addr, tx) \
    asm volatile("mbarrier.arrive.expect_tx.shared.b64 _, [%0], %1;" \
                 :: "r"(addr), "r"(tx) : "memory")
#define MBARRIER_WAIT_PARITY(mbar_addr, phase_parity) do {                                 \
    uint32_t _mbar = (uint32_t)(mbar_addr);                                                \
    uint32_t _parity = (uint32_t)(phase_parity);                                           \
    uint32_t _done;                                                                        \
    asm volatile(                                                                          \
        "{\n\t.reg .pred p;\n\t"                                                           \
        "mbarrier.try_wait.parity.acquire.cta.shared::cta.b64 p, [%1], %2;\n\t"            \
        "selp.b32 %0, 1, 0, p;\n\t}"                                                       \
        : "=r"(_done) : "r"(_mbar), "r"(_parity) : "memory");                              \
    if (!_done) {                                                                          \
        asm volatile(                                                                      \
            "{\n\t.reg .pred P1;\n\t"                                                      \
            "WAIT_LOOP_%=:\n\t"                                                            \
            "mbarrier.try_wait.parity.acquire.cta.shared::cta.b64 P1, [%0], %1, 0x989680;\n\t" \
            "@P1 bra.uni WAIT_DONE_%=;\n\t"                                                \
            "bra.uni WAIT_LOOP_%=;\n\t"                                                    \
            "WAIT_DONE_%=:\n\t}"                                                           \
            :: "r"(_mbar), "r"(_parity) : "memory");                                       \
    }                                                                                      \
} while (0)

#define BULK_G2S(dst_smem, src_gmem, bytes, mbar) \
    asm volatile("cp.async.bulk.shared::cluster.global.mbarrier::complete_tx::bytes " \
                 "[%0], [%1], %2, [%3];" \
                 :: "r"(dst_smem), "l"(src_gmem), "r"(bytes), "r"(mbar) : "memory")

__device__ __forceinline__ void mma_f16(float (&c)[4], uint32_t a0, uint32_t a1,
                                        uint32_t a2, uint32_t a3,
                                        uint32_t b0, uint32_t b1) {
    asm volatile(
        "mma.sync.aligned.m16n8k16.row.col.f32.f16.f16.f32 "
        "{%0,%1,%2,%3}, {%4,%5,%6,%7}, {%8,%9}, {%0,%1,%2,%3};"
        : "+f"(c[0]), "+f"(c[1]), "+f"(c[2]), "+f"(c[3])
        : "r"(a0), "r"(a1), "r"(a2), "r"(a3), "r"(b0), "r"(b1));
}

// ================= prep: all fp16 layouts =================
__global__ void prep_kernel(const float* __restrict__ W_hh,
                            const float* __restrict__ W_ih,
                            const float* __restrict__ hxs,
                            const float* __restrict__ X) {
    int idx = blockIdx.x * blockDim.x + threadIdx.x;
    if (idx < G3 * HH) {
        int r = idx >> 9, k = idx & 511;
        int gg = r >> 9, u = r & 511, s = u >> 5, c = u & 31;
        int cr = (c >> 3) * 24 + gg * 8 + (c & 7);
        int kst = k >> 6, kk = k & 63;
        g_Whh2h[((s * 8 + kst) * 96 + cr) * 64 + (kk ^ (16 * (cr & 3)))] =
            __float2half_rn(W_hh[idx]);
    }
    if (idx < G3 * II) {
        int r = idx >> 6, k = idx & 63;
        int gg = r >> 9, u = r & 511, s = u >> 5, c = u & 31;
        int cr = (c >> 3) * 24 + gg * 8 + (c & 7);
        g_Wih_h[(s * 96 + cr) * 64 + (k ^ (16 * (cr & 3)))] = __float2half_rn(W_ih[idx]);
    }
    if (idx < NN * HH) {
        int n = idx >> 9, k = idx & 511;
        int kst = k >> 6, kk = k & 63;
        g_hA2h[0][(kst * NN + n) * 64 + (kk ^ (16 * (n & 3)))] =
            __float2half_rn(hxs[idx]);
    }
    if (idx < TT * NN * II) {
        int tn = idx >> 6, k = idx & 63;
        int n = tn & 1023;
        g_Xh[(size_t)tn * 64 + (k ^ (16 * (n & 3)))] = __float2half_rn(X[idx]);
    }
}

// ================= per-step kernel: PDL, x-stage pre-sync ======================
#define XW_OFF 0                        // x 8 KB @0, Wih 12 KB @8192
#define HSTG 20480                      // 2 x 40960 h-stage buffers
#define MB_OFF (HSTG + 2 * 40960)       // mbX @0, mbF0 @8, mbF1 @16
#define SMEM_STEP (MB_OFF + 64)         // 102464 -> 2 CTAs/SM

__global__ __launch_bounds__(NTH, 2)
void gru_step(const __half* __restrict__ hA,     // [kst64][1024][64] swizzled
              __half* __restrict__ hA_next,
              const float* __restrict__ h_prev,  // fp32 [1024][512]
              const float* __restrict__ m_t,
              const __half* __restrict__ X_t,    // [1024][64] swizzled (this t)
              const __half* __restrict__ Whh2,
              const __half* __restrict__ Wih,
              const float* __restrict__ b_ih,
              const float* __restrict__ b_hh,
              float* __restrict__ h_out,
              float* __restrict__ h_out2) {
    extern __shared__ char smem[];
    const uint32_t sbase = smem_u32(smem);
    const int tid = threadIdx.x;
    const int strip = blockIdx.x;      // 0..15
    const int rb = blockIdx.y * 64;    // 0..960

    const uint32_t mbX = sbase + MB_OFF;
    const uint32_t mbF = mbX + 8;

    const int w = tid >> 5, lane = tid & 31, g = lane >> 2, t = lane & 3;
    const int wr = w & 1, wc = w >> 1;
    const int r00 = wr * 32 + g;
    const int r10 = r00 + 16;
    const int crb = wc * 24 + g;
    const int g3m = g & 3;
    const int t2 = 2 * t;
    const int hc = wc * 8 + t2;

    if (tid == 0) {
        MBARRIER_INIT(mbX, 1);
        MBARRIER_INIT(mbF, 1);
        MBARRIER_INIT(mbF + 8, 1);
    }
    __syncthreads();

    // ===== PRE-SYNC: step-independent prefetches + x-GEMM =====
    const __half* Bsrc = Whh2 + (size_t)strip * 8 * 96 * 64;
    if (tid == 0) {
        MBARRIER_EXPECT_TX(mbX, 20480);
        BULK_G2S(sbase + XW_OFF, X_t + (size_t)rb * 64, 8192, mbX);
        BULK_G2S(sbase + XW_OFF + 8192, Wih + (size_t)strip * 96 * 64, 12288, mbX);
        #pragma unroll
        for (int s = 0; s < 2; s++) {
            const uint32_t hb = sbase + HSTG + s * 40960;
            MBARRIER_EXPECT_TX(mbF + 8 * s, 40960);          // covers B now + A later
            BULK_G2S(hb + 16384, Bsrc + (size_t)(2 * s) * 96 * 64, 12288, mbF + 8 * s);
            BULK_G2S(hb + 28672, Bsrc + (size_t)(2 * s + 1) * 96 * 64, 12288,
                     mbF + 8 * s);
        }
    }
    const int gcol = strip * 32 + hc;
    const float2 bir = *reinterpret_cast<const float2*>(&b_ih[gcol]);
    const float2 biz = *reinterpret_cast<const float2*>(&b_ih[512 + gcol]);
    const float2 bin = *reinterpret_cast<const float2*>(&b_ih[1024 + gcol]);
    const float2 bhr = *reinterpret_cast<const float2*>(&b_hh[gcol]);
    const float2 bhz = *reinterpret_cast<const float2*>(&b_hh[512 + gcol]);
    const float2 bhn = *reinterpret_cast<const float2*>(&b_hh[1024 + gcol]);
    // pre-summed r/z bias (n-gate biases must stay separate: r multiplies bhn)
    const float brs0 = bir.x + bhr.x, brs1 = bir.y + bhr.y;
    const float bzs0 = biz.x + bhz.x, bzs1 = biz.y + bhz.y;

    // masks: step-independent, load pre-sync
    float mreg[2][2];
    #pragma unroll
    for (int f = 0; f < 2; f++)
        #pragma unroll
        for (int rs = 0; rs < 2; rs++)
            mreg[f][rs] = m_t[rb + wr * 32 + f * 16 + g + 8 * rs];

    float acc[2][3][4];
    float accxn[2][4];
    #pragma unroll
    for (int f = 0; f < 2; f++) {
        #pragma unroll
        for (int j = 0; j < 3; j++)
            #pragma unroll
            for (int q = 0; q < 4; q++) acc[f][j][q] = 0.0f;
        #pragma unroll
        for (int q = 0; q < 4; q++) accxn[f][q] = 0.0f;
    }

    // ---- x stage (K=64) — fully pre-sync ----
    {
        MBARRIER_WAIT_PARITY(mbX, 0);
        const __half* As = (const __half*)(smem + XW_OFF);
        const __half* Bs = (const __half*)(smem + XW_OFF + 8192);
        #pragma unroll
        for (int c = 0; c < 4; c++) {
            const int koff = ((c ^ g3m) * 16) + 4 * t;
            uint2 a00 = *reinterpret_cast<const uint2*>(&As[r00 * 64 + koff]);
            uint2 a01 = *reinterpret_cast<const uint2*>(&As[(r00 + 8) * 64 + koff]);
            uint2 a10 = *reinterpret_cast<const uint2*>(&As[r10 * 64 + koff]);
            uint2 a11 = *reinterpret_cast<const uint2*>(&As[(r10 + 8) * 64 + koff]);
            uint2 b0 = *reinterpret_cast<const uint2*>(&Bs[crb * 64 + koff]);
            uint2 b1 = *reinterpret_cast<const uint2*>(&Bs[(crb + 8) * 64 + koff]);
            uint2 b2 = *reinterpret_cast<const uint2*>(&Bs[(crb + 16) * 64 + koff]);
            mma_f16(acc[0][0], a00.x, a01.x, a00.y, a01.y, b0.x, b0.y);
            mma_f16(acc[0][1], a00.x, a01.x, a00.y, a01.y, b1.x, b1.y);
            mma_f16(accxn[0],  a00.x, a01.x, a00.y, a01.y, b2.x, b2.y);
            mma_f16(acc[1][0], a10.x, a11.x, a10.y, a11.y, b0.x, b0.y);
            mma_f16(acc[1][1], a10.x, a11.x, a10.y, a11.y, b1.x, b1.y);
            mma_f16(accxn[1],  a10.x, a11.x, a10.y, a11.y, b2.x, b2.y);
        }
    }

    // ===== wait for the previous step's kernel to fully complete =====
    cudaGridDependencySynchronize();
    cudaTriggerProgrammaticLaunchCompletion();

    // ===== POST-SYNC: dependent loads (hA bulks first, then h_prev regs) =====
    if (tid == 0) {
        #pragma unroll
        for (int s = 0; s < 2; s++) {
            const uint32_t hb = sbase + HSTG + s * 40960;
            BULK_G2S(hb,        hA + ((size_t)(2 * s) * NN + rb) * 64, 8192, mbF + 8 * s);
            BULK_G2S(hb + 8192, hA + ((size_t)(2 * s + 1) * NN + rb) * 64, 8192,
                     mbF + 8 * s);
        }
    }
    float2 hpr[2][2];
    #pragma unroll
    for (int f = 0; f < 2; f++)
        #pragma unroll
        for (int rs = 0; rs < 2; rs++) {
            const int R = rb + wr * 32 + f * 16 + g + 8 * rs;
            hpr[f][rs] = *reinterpret_cast<const float2*>(
                &h_prev[(size_t)R * HH + strip * 32 + hc]);
        }

    // ---- 4 h stages (K=128 each), NBUF=2 ----
    #pragma unroll
    for (int s = 0; s < 4; s++) {
        const int buf = s & 1;
        MBARRIER_WAIT_PARITY(mbF + 8 * buf, (s >> 1) & 1);
        const __half* As = (const __half*)(smem + HSTG + buf * 40960);
        const __half* Bs = (const __half*)(smem + HSTG + buf * 40960 + 16384);
        #pragma unroll
        for (int k8 = 0; k8 < 8; k8++) {
            const __half* Asub = As + ((k8 >= 4) ? 4096 : 0);
            const __half* Bsub = Bs + ((k8 >= 4) ? 6144 : 0);
            const int koff = (((k8 & 3) ^ g3m) * 16) + 4 * t;
            uint2 a00 = *reinterpret_cast<const uint2*>(&Asub[r00 * 64 + koff]);
            uint2 a01 = *reinterpret_cast<const uint2*>(&Asub[(r00 + 8) * 64 + koff]);
            uint2 a10 = *reinterpret_cast<const uint2*>(&Asub[r10 * 64 + koff]);
            uint2 a11 = *reinterpret_cast<const uint2*>(&Asub[(r10 + 8) * 64 + koff]);
            uint2 b0 = *reinterpret_cast<const uint2*>(&Bsub[crb * 64 + koff]);
            uint2 b1 = *reinterpret_cast<const uint2*>(&Bsub[(crb + 8) * 64 + koff]);
            uint2 b2 = *reinterpret_cast<const uint2*>(&Bsub[(crb + 16) * 64 + koff]);
            mma_f16(acc[0][0], a00.x, a01.x, a00.y, a01.y, b0.x, b0.y);
            mma_f16(acc[0][1], a00.x, a01.x, a00.y, a01.y, b1.x, b1.y);
            mma_f16(acc[0][2], a00.x, a01.x, a00.y, a01.y, b2.x, b2.y);
            mma_f16(acc[1][0], a10.x, a11.x, a10.y, a11.y, b0.x, b0.y);
            mma_f16(acc[1][1], a10.x, a11.x, a10.y, a11.y, b1.x, b1.y);
            mma_f16(acc[1][2], a10.x, a11.x, a10.y, a11.y, b2.x, b2.y);
        }
        if (s < 2) {
            __syncthreads();
            if (tid == 0) {
                const int s2 = s + 2;
                const uint32_t hb = sbase + HSTG + buf * 40960;
                MBARRIER_EXPECT_TX(mbF + 8 * buf, 40960);
                BULK_G2S(hb,         hA + ((size_t)(2 * s2) * NN + rb) * 64, 8192,
                         mbF + 8 * buf);
                BULK_G2S(hb + 8192,  hA + ((size_t)(2 * s2 + 1) * NN + rb) * 64, 8192,
                         mbF + 8 * buf);
                BULK_G2S(hb + 16384, Bsrc + (size_t)(2 * s2) * 96 * 64, 12288,
                         mbF + 8 * buf);
                BULK_G2S(hb + 28672, Bsrc + (size_t)(2 * s2 + 1) * 96 * 64, 12288,
                         mbF + 8 * buf);
            }
        }
    }

    // ---- fragment-direct epilogue (fast activations) ----
    const int kstO = strip >> 1;
    const int khO = (strip & 1) * 32 + hc;

    #pragma unroll
    for (int f = 0; f < 2; f++) {
        #pragma unroll
        for (int rs = 0; rs < 2; rs++) {
            const int Rl = wr * 32 + f * 16 + g + 8 * rs;
            const int R = rb + Rl;
            const float m = mreg[f][rs];
            const float sr0 = acc[f][0][2 * rs], sr1 = acc[f][0][2 * rs + 1];
            const float sz0 = acc[f][1][2 * rs], sz1 = acc[f][1][2 * rs + 1];
            const float sn0 = acc[f][2][2 * rs], sn1 = acc[f][2][2 * rs + 1];
            const float xn0 = accxn[f][2 * rs],  xn1 = accxn[f][2 * rs + 1];
            const float2 hp = hpr[f][rs];

            float rv0 = sigf(fmaf(m, sr0, brs0));
            float rv1 = sigf(fmaf(m, sr1, brs1));
            float zv0 = sigf(fmaf(m, sz0, bzs0));
            float zv1 = sigf(fmaf(m, sz1, bzs1));
            float nv0 = tanhf_fast(fmaf(m, xn0, bin.x) + rv0 * fmaf(m, sn0, bhn.x));
            float nv1 = tanhf_fast(fmaf(m, xn1, bin.y) + rv1 * fmaf(m, sn1, bhn.y));
            float h0 = fmaf(zv0, fmaf(m, hp.x, -nv0), nv0);
            float h1 = fmaf(zv1, fmaf(m, hp.y, -nv1), nv1);

            *reinterpret_cast<float2*>(&h_out[(size_t)R * HH + gcol]) =
                make_float2(h0, h1);
            if (h_out2)
                *reinterpret_cast<float2*>(&h_out2[(size_t)R * HH + gcol]) =
                    make_float2(h0, h1);
            __half2 oc = __floats2half2_rn(h0, h1);
            *reinterpret_cast<__half2*>(
                &hA_next[((size_t)kstO * NN + R) * 64 + (khO ^ (16 * (R & 3)))]) = oc;
        }
    }
}

// ---------------- host ----------------
extern "C" void kernel_launch(void* const* d_in, const int* in_sizes, int n_in,
                              void* d_out, int out_size) {
    const float* hxs   = (const float*)d_in[0];
    const float* masks = (const float*)d_in[2];
    const float* pact  = (const float*)d_in[3];
    const float* W_ih  = (const float*)d_in[4];
    const float* W_hh  = (const float*)d_in[5];
    const float* b_ih  = (const float*)d_in[6];
    const float* b_hh  = (const float*)d_in[7];
    float* out = (float*)d_out;

    static bool attr_set = false;
    if (!attr_set) {
        cudaFuncSetAttribute(gru_step, cudaFuncAttributeMaxDynamicSharedMemorySize,
                             SMEM_STEP);
        attr_set = true;
    }

    static __half* hA0 = nullptr;
    static __half* gX = nullptr;
    static __half* gW2 = nullptr;
    static __half* gWi = nullptr;
    if (!hA0) cudaGetSymbolAddress((void**)&hA0, g_hA2h);
    if (!gX)  cudaGetSymbolAddress((void**)&gX, g_Xh);
    if (!gW2) cudaGetSymbolAddress((void**)&gW2, g_Whh2h);
    if (!gWi) cudaGetSymbolAddress((void**)&gWi, g_Wih_h);

    // 1) prep
    {
        int total = TT * NN * II;
        prep_kernel<<<(total + 255) / 256, 256>>>(W_hh, W_ih, hxs, pact);
    }

    // 2) sequential steps with PDL chaining
    const size_t stepElems = (size_t)NN * HH;
    const size_t hASz = (size_t)8 * NN * 64;
    const bool has_tail = (size_t)out_size >= (size_t)TT * stepElems + stepElems;

    dim3 grid(NSTRIP, NN / 64);                  // (16, 16) = 256 CTAs, 2/SM
    for (int tstep = 0; tstep < TT; tstep++) {
        const float* h_prev = (tstep == 0) ? hxs : out + (size_t)(tstep - 1) * stepElems;
        float* h_out  = out + (size_t)tstep * stepElems;
        float* h_out2 = (tstep == TT - 1 && has_tail) ? out + (size_t)TT * stepElems
                                                      : nullptr;
        const __half* hA_cur  = hA0 + (size_t)(tstep & 1) * hASz;
        __half*       hA_next = hA0 + (size_t)((tstep + 1) & 1) * hASz;
        const __half* X_t = gX + (size_t)tstep * NN * II;
        const float* m_p = masks + (size_t)tstep * NN;

        cudaLaunchConfig_t cfg = {};
        cfg.gridDim = grid;
        cfg.blockDim = dim3(NTH, 1, 1);
        cfg.dynamicSmemBytes = SMEM_STEP;
        cfg.stream = 0;
        cudaLaunchAttribute attrs[1];
        attrs[0].id = cudaLaunchAttributeProgrammaticStreamSerialization;
        attrs[0].val.programmaticStreamSerializationAllowed = 1;
        cfg.attrs = attrs;
        cfg.numAttrs = (tstep == 0) ? 0 : 1;

        cudaLaunchKernelEx(&cfg, gru_step,
                           hA_cur, hA_next, h_prev, m_p, X_t,
                           (const __half*)gW2, (const __half*)gWi,
                           b_ih, b_hh, h_out, h_out2);
    }
}